// round 1
// baseline (speedup 1.0000x reference)
#include <cuda_runtime.h>
#include <cuda_bf16.h>
#include <cstddef>

#define B_ 8
#define N_ 512
#define T_ 2048
#define E_ 4096
#define D_ 768
#define TD_ 128
#define L_ 4
#define F_ (TD_ + D_)   /* 896 */
#define G_ (3 * D_)     /* 2304 */
#define M_ (B_ * N_)    /* 4096 */

// ---------------- scratch (static __device__, no allocation) ----------------
__device__ float g_text [M_ * D_];   // per-node token sum
__device__ float g_fused[M_ * F_];   // [type_e | text_mean]
__device__ float g_h    [M_ * D_];
__device__ float g_msg  [M_ * D_];
__device__ float g_agg  [M_ * D_];
__device__ float g_gi   [M_ * G_];
__device__ float g_gh   [M_ * G_];

// ---------------- helpers ----------------
__global__ void k_zero(float4* __restrict__ p, int n4) {
    int i = blockIdx.x * blockDim.x + threadIdx.x;
    if (i < n4) p[i] = make_float4(0.f, 0.f, 0.f, 0.f);
}

// one block per (b, t): gather word_emb row, atomic-add into its segment row
__global__ void k_segsum(const int* __restrict__ tok, const int* __restrict__ seg,
                         const float* __restrict__ emb, float* __restrict__ out) {
    int bt = blockIdx.x;          // 0 .. B*T-1
    int b  = bt / T_;
    int t  = tok[bt];
    int s  = seg[bt];
    const float4* src = (const float4*)(emb + (size_t)t * D_);
    float* dst = out + ((size_t)b * N_ + s) * D_;
    int d = threadIdx.x;          // 192 threads * 4 floats = 768
    float4 v = src[d];
    atomicAdd(dst + d * 4 + 0, v.x);
    atomicAdd(dst + d * 4 + 1, v.y);
    atomicAdd(dst + d * 4 + 2, v.z);
    atomicAdd(dst + d * 4 + 3, v.w);
}

// build fused[b,n,:] = [type_table[type] (128) | text_sum/len (768)]
__global__ void k_fused(const int* __restrict__ types, const int* __restrict__ lens,
                        const float* __restrict__ table, const float* __restrict__ tsum,
                        float* __restrict__ fused) {
    int bn = blockIdx.x;
    float inv = 1.0f / (float)lens[bn];
    const float* tt = table + (size_t)types[bn] * TD_;
    const float* ts = tsum + (size_t)bn * D_;
    float* o = fused + (size_t)bn * F_;
    int tid = threadIdx.x;        // 256
    if (tid < TD_) o[tid] = tt[tid];
    #pragma unroll
    for (int d = tid; d < D_; d += 256) o[TD_ + d] = ts[d] * inv;
}

// one block per (b, e): agg[b,dst] += msg[b,src] * w
__global__ void k_scatter(const int* __restrict__ esrc, const int* __restrict__ edst,
                          const float* __restrict__ ew, const float* __restrict__ msg,
                          float* __restrict__ agg) {
    int be = blockIdx.x;          // 0 .. B*E-1
    int b  = be / E_;
    int s  = esrc[be];
    int t  = edst[be];
    float w = ew[be];
    const float4* mp = (const float4*)(msg + ((size_t)b * N_ + s) * D_);
    float* ap = agg + ((size_t)b * N_ + t) * D_;
    int d = threadIdx.x;          // 192
    float4 v = mp[d];
    atomicAdd(ap + d * 4 + 0, v.x * w);
    atomicAdd(ap + d * 4 + 1, v.y * w);
    atomicAdd(ap + d * 4 + 2, v.z * w);
    atomicAdd(ap + d * 4 + 3, v.w * w);
}

__global__ void k_gru(const float* __restrict__ gi, const float* __restrict__ gh,
                      float* __restrict__ h) {
    int row = blockIdx.x;         // 4096
    const float* gip = gi + (size_t)row * G_;
    const float* ghp = gh + (size_t)row * G_;
    float* hp = h + (size_t)row * D_;
    #pragma unroll
    for (int d = threadIdx.x; d < D_; d += 256) {
        float ir = gip[d], iz = gip[D_ + d], in = gip[2 * D_ + d];
        float hr = ghp[d], hz = ghp[D_ + d], hn = ghp[2 * D_ + d];
        float r = 1.0f / (1.0f + expf(-(ir + hr)));
        float z = 1.0f / (1.0f + expf(-(iz + hz)));
        float n = tanhf(in + r * hn);
        hp[d] = (1.0f - z) * n + z * hp[d];
    }
}

// masked copy: out[b,w,:] = (w < min(keep[b],512)) ? h[b,w,:] : 0
__global__ void k_out(const float* __restrict__ h, const int* __restrict__ keep,
                      float* __restrict__ out) {
    int bw = blockIdx.x;          // 0 .. B*512-1 (W == N here)
    int b  = bw >> 9;
    int wn = bw & 511;
    int kp = keep[b]; if (kp > 512) kp = 512;
    bool valid = wn < kp;
    const float4* hp = (const float4*)(h + (size_t)bw * D_);
    float4* op = (float4*)(out + (size_t)bw * D_);
    int d = threadIdx.x;          // 192
    float4 v = valid ? hp[d] : make_float4(0.f, 0.f, 0.f, 0.f);
    op[d] = v;
}

// ---------------- fp32 SIMT GEMM: C[M,N] = A[M,K] * B (+bias) ----------------
// TB=false: B is [K,N] row-major.  TB=true: B is [N,K] row-major (C = A*B^T).
// 128x128 block tile, BK=8, 256 threads, 8x8 per thread. All dims assumed
// divisible (M%128==0, N%128==0, K%8==0) — true for every call here.
template<bool TB>
__global__ void __launch_bounds__(256, 2) gemm128(
    const float* __restrict__ A, const float* __restrict__ Bm,
    const float* __restrict__ bias, float* __restrict__ C,
    int M, int N, int K)
{
    __shared__ float As[8][132];
    __shared__ float Bs[8][132];

    int tid = threadIdx.x;
    int bm  = blockIdx.y, bn = blockIdx.x;
    int rl  = tid >> 1;            // 0..127
    int kh  = (tid & 1) << 2;      // 0 or 4
    int tx  = tid & 15, ty = tid >> 4;

    const float* Ap = A + ((size_t)(bm * 128) + rl) * K + kh;
    const float* Bp;
    if (TB) Bp = Bm + ((size_t)(bn * 128) + rl) * K + kh;
    else    Bp = Bm + (size_t)(tid >> 5) * N + bn * 128 + ((tid & 31) << 2);

    float acc[8][8];
    #pragma unroll
    for (int i = 0; i < 8; i++)
        #pragma unroll
        for (int j = 0; j < 8; j++) acc[i][j] = 0.f;

    for (int k0 = 0; k0 < K; k0 += 8) {
        float4 av = *(const float4*)(Ap + k0);
        As[kh + 0][rl] = av.x; As[kh + 1][rl] = av.y;
        As[kh + 2][rl] = av.z; As[kh + 3][rl] = av.w;
        if (TB) {
            float4 bv = *(const float4*)(Bp + k0);
            Bs[kh + 0][rl] = bv.x; Bs[kh + 1][rl] = bv.y;
            Bs[kh + 2][rl] = bv.z; Bs[kh + 3][rl] = bv.w;
        } else {
            float4 bv = *(const float4*)(Bp + (size_t)k0 * N);
            *(float4*)&Bs[tid >> 5][(tid & 31) << 2] = bv;
        }
        __syncthreads();
        #pragma unroll
        for (int kk = 0; kk < 8; kk++) {
            float4 a0 = *(const float4*)&As[kk][ty << 2];
            float4 a1 = *(const float4*)&As[kk][(ty << 2) + 64];
            float4 b0 = *(const float4*)&Bs[kk][tx << 2];
            float4 b1 = *(const float4*)&Bs[kk][(tx << 2) + 64];
            float a[8] = {a0.x, a0.y, a0.z, a0.w, a1.x, a1.y, a1.z, a1.w};
            float b[8] = {b0.x, b0.y, b0.z, b0.w, b1.x, b1.y, b1.z, b1.w};
            #pragma unroll
            for (int i = 0; i < 8; i++)
                #pragma unroll
                for (int j = 0; j < 8; j++)
                    acc[i][j] += a[i] * b[j];
        }
        __syncthreads();
    }

    // epilogue
    float bvj[8];
    #pragma unroll
    for (int j = 0; j < 8; j++) {
        int col = bn * 128 + ((j < 4) ? (tx << 2) + j : 64 + (tx << 2) + j - 4);
        bvj[j] = bias ? bias[col] : 0.f;
    }
    #pragma unroll
    for (int i = 0; i < 8; i++) {
        int row = bm * 128 + ((i < 4) ? (ty << 2) + i : 64 + (ty << 2) + i - 4);
        float* Cp = C + (size_t)row * N + bn * 128;
        float4 c0 = make_float4(acc[i][0] + bvj[0], acc[i][1] + bvj[1],
                                acc[i][2] + bvj[2], acc[i][3] + bvj[3]);
        float4 c1 = make_float4(acc[i][4] + bvj[4], acc[i][5] + bvj[5],
                                acc[i][6] + bvj[6], acc[i][7] + bvj[7]);
        *(float4*)(Cp + (tx << 2))      = c0;
        *(float4*)(Cp + 64 + (tx << 2)) = c1;
    }
}

// ---------------- launch ----------------
extern "C" void kernel_launch(void* const* d_in, const int* in_sizes, int n_in,
                              void* d_out, int out_size) {
    const int*   node_types = (const int*)d_in[0];
    const int*   tok_ids    = (const int*)d_in[1];
    const int*   seg_ids    = (const int*)d_in[2];
    const int*   tok_lens   = (const int*)d_in[3];
    const int*   gnode_lens = (const int*)d_in[4];
    const int*   esrc       = (const int*)d_in[5];
    const int*   edst       = (const int*)d_in[6];
    const float* ew         = (const float*)d_in[7];
    const float* type_table = (const float*)d_in[8];
    const float* word_emb   = (const float*)d_in[9];
    const float* fusion_w   = (const float*)d_in[10];
    const float* fusion_b   = (const float*)d_in[11];
    const float* ggnn_w     = (const float*)d_in[12];
    const float* w_ih       = (const float*)d_in[13];
    const float* w_hh       = (const float*)d_in[14];
    const float* b_ih       = (const float*)d_in[15];
    const float* b_hh       = (const float*)d_in[16];
    float* out = (float*)d_out;

    float *text, *fused, *h, *msg, *agg, *gi, *gh;
    cudaGetSymbolAddress((void**)&text,  g_text);
    cudaGetSymbolAddress((void**)&fused, g_fused);
    cudaGetSymbolAddress((void**)&h,     g_h);
    cudaGetSymbolAddress((void**)&msg,   g_msg);
    cudaGetSymbolAddress((void**)&agg,   g_agg);
    cudaGetSymbolAddress((void**)&gi,    g_gi);
    cudaGetSymbolAddress((void**)&gh,    g_gh);

    const int n4 = M_ * D_ / 4;

    // embeddings + segment mean + fusion input
    k_zero<<<(n4 + 255) / 256, 256>>>((float4*)text, n4);
    k_segsum<<<B_ * T_, 192>>>(tok_ids, seg_ids, word_emb, text);
    k_fused<<<M_, 256>>>(node_types, tok_lens, type_table, text, fused);

    // h = fused @ fusion_w + fusion_b
    gemm128<false><<<dim3(D_ / 128, M_ / 128), 256>>>(fused, fusion_w, fusion_b, h, M_, D_, F_);

    for (int l = 0; l < L_; ++l) {
        // msg = h @ ggnn_w[l]
        gemm128<false><<<dim3(D_ / 128, M_ / 128), 256>>>(
            h, ggnn_w + (size_t)l * D_ * D_, nullptr, msg, M_, D_, D_);
        // agg = scatter_add(msg[src] * w -> dst)
        k_zero<<<(n4 + 255) / 256, 256>>>((float4*)agg, n4);
        k_scatter<<<B_ * E_, 192>>>(esrc, edst, ew, msg, agg);
        // gi = agg @ w_ih^T + b_ih ; gh = h @ w_hh^T + b_hh
        gemm128<true><<<dim3(G_ / 128, M_ / 128), 256>>>(agg, w_ih, b_ih, gi, M_, G_, D_);
        gemm128<true><<<dim3(G_ / 128, M_ / 128), 256>>>(h,   w_hh, b_hh, gh, M_, G_, D_);
        // GRU update (in place on h)
        k_gru<<<M_, 256>>>(gi, gh, h);
    }

    k_out<<<M_, 192>>>(h, gnode_lens, out);
}

// round 3
// speedup vs baseline: 1.6191x; 1.6191x over previous
#include <cuda_runtime.h>
#include <cuda_bf16.h>
#include <cstdint>
#include <cstddef>

#define B_ 8
#define N_ 512
#define T_ 2048
#define E_ 4096
#define D_ 768
#define TD_ 128
#define L_ 4
#define F_ (TD_ + D_)   /* 896 */
#define G_ (3 * D_)     /* 2304 */
#define M_ (B_ * N_)    /* 4096 */

// ---------------- fp32 scratch ----------------
__device__ float g_text [M_ * D_];
__device__ float g_fused[M_ * F_];
__device__ float g_h    [M_ * D_];
__device__ float g_msg  [M_ * D_];
__device__ float g_agg  [M_ * D_];
__device__ float g_gi   [M_ * G_];
__device__ float g_gh   [M_ * G_];

// ---------------- bf16 split scratch ----------------
__device__ __nv_bfloat16 s_f_hi [M_ * F_];
__device__ __nv_bfloat16 s_f_lo [M_ * F_];
__device__ __nv_bfloat16 s_h_hi [M_ * D_];
__device__ __nv_bfloat16 s_h_lo [M_ * D_];
__device__ __nv_bfloat16 s_a_hi [M_ * D_];
__device__ __nv_bfloat16 s_a_lo [M_ * D_];
__device__ __nv_bfloat16 s_fw_hi[D_ * F_];      // fusion_w^T  [768][896]
__device__ __nv_bfloat16 s_fw_lo[D_ * F_];
__device__ __nv_bfloat16 s_gw_hi[L_ * D_ * D_]; // ggnn_w[l]^T [768][768]
__device__ __nv_bfloat16 s_gw_lo[L_ * D_ * D_];
__device__ __nv_bfloat16 s_ih_hi[G_ * D_];      // w_ih [2304][768]
__device__ __nv_bfloat16 s_ih_lo[G_ * D_];
__device__ __nv_bfloat16 s_hh_hi[G_ * D_];
__device__ __nv_bfloat16 s_hh_lo[G_ * D_];

// ================= helpers =================
__device__ __forceinline__ uint32_t smem_u32(const void* p) {
    uint32_t a;
    asm("{ .reg .u64 t; cvta.to.shared.u64 t, %1; cvt.u32.u64 %0, t; }" : "=r"(a) : "l"(p));
    return a;
}
__device__ __forceinline__ void cp16(uint32_t saddr, const void* g) {
    asm volatile("cp.async.cg.shared.global [%0], [%1], 16;" :: "r"(saddr), "l"(g) : "memory");
}
#define CP_COMMIT() asm volatile("cp.async.commit_group;" ::: "memory")
#define CP_WAIT1()  asm volatile("cp.async.wait_group 1;" ::: "memory")

__device__ __forceinline__ void ldsm4(uint32_t& r0, uint32_t& r1, uint32_t& r2,
                                      uint32_t& r3, uint32_t a) {
    asm volatile("ldmatrix.sync.aligned.m8n8.x4.shared.b16 {%0,%1,%2,%3}, [%4];"
                 : "=r"(r0), "=r"(r1), "=r"(r2), "=r"(r3) : "r"(a));
}
__device__ __forceinline__ void mma16816(float* d, const uint32_t* a, const uint32_t* b) {
    asm volatile(
        "mma.sync.aligned.m16n8k16.row.col.f32.bf16.bf16.f32 "
        "{%0,%1,%2,%3}, {%4,%5,%6,%7}, {%8,%9}, {%0,%1,%2,%3};"
        : "+f"(d[0]), "+f"(d[1]), "+f"(d[2]), "+f"(d[3])
        : "r"(a[0]), "r"(a[1]), "r"(a[2]), "r"(a[3]), "r"(b[0]), "r"(b[1]));
}

// smem tile geometry: 128 rows x 32 bf16 (64B) + 16B pad -> 80B row stride
#define ROWB    80
#define TILE_BYTES (128 * ROWB)          /* 10240 */
#define STAGE_BYTES (2 * TILE_BYTES)     /* A + B  = 20480 */
#define STAGES  3
#define SMEM_SZ (STAGES * STAGE_BYTES)   /* 61440 */

// ================= mma.sync split-bf16 GEMM =================
// C[M,N] = (Ahi+Alo)[M,K] @ (Bhi+Blo)[N,K]^T  (3-term), + optional bias.
// grid=(N/128, M/128), block=256, dyn smem = SMEM_SZ. K%32==0, N%128==0.
__global__ void __launch_bounds__(256) bmma(
    const __nv_bfloat16* __restrict__ Ahi, const __nv_bfloat16* __restrict__ Alo,
    const __nv_bfloat16* __restrict__ Bhi, const __nv_bfloat16* __restrict__ Blo,
    const float* __restrict__ bias, float* __restrict__ C, int N, int K)
{
    extern __shared__ char smem[];
    const uint32_t sbase = smem_u32(smem);
    const int tid = threadIdx.x;
    const int wid = tid >> 5, lane = tid & 31;
    const int wm = wid & 3, wn = wid >> 2;           // 4x2 warp grid
    const int bn = blockIdx.x, bm = blockIdx.y;

    const int nkc = K >> 5;            // 32-wide chunks per split part
    const int chunks = 3 * nkc;

    // per-thread load assignment: 2 x 16B for A, 2 x 16B for B per chunk
    const int lrow0 = tid >> 2;            // rows 0..63   (idx = tid)
    const int lrow1 = (tid + 256) >> 2;    // rows 64..127 (idx = tid+256)
    const int lseg0 = tid & 3;
    const int lseg1 = (tid + 256) & 3;     // == lseg0

    auto load_tile = [&](int stage, int c) {
        int part = c / nkc, kc = c - part * nkc;
        const __nv_bfloat16* Ag = (part == 1) ? Alo : Ahi;
        const __nv_bfloat16* Bg = (part == 2) ? Blo : Bhi;
        uint32_t sa = sbase + stage * STAGE_BYTES;
        uint32_t sb = sa + TILE_BYTES;
        int kof = kc * 32;
        cp16(sa + lrow0 * ROWB + lseg0 * 16,
             Ag + (size_t)(bm * 128 + lrow0) * K + kof + lseg0 * 8);
        cp16(sa + lrow1 * ROWB + lseg1 * 16,
             Ag + (size_t)(bm * 128 + lrow1) * K + kof + lseg1 * 8);
        cp16(sb + lrow0 * ROWB + lseg0 * 16,
             Bg + (size_t)(bn * 128 + lrow0) * K + kof + lseg0 * 8);
        cp16(sb + lrow1 * ROWB + lseg1 * 16,
             Bg + (size_t)(bn * 128 + lrow1) * K + kof + lseg1 * 8);
        CP_COMMIT();
    };

    float acc[2][8][4];
    #pragma unroll
    for (int i = 0; i < 2; i++)
        #pragma unroll
        for (int j = 0; j < 8; j++)
            #pragma unroll
            for (int q = 0; q < 4; q++) acc[i][j][q] = 0.f;

    // prologue: fill STAGES-1 stages
    load_tile(0, 0);
    load_tile(1, 1);

    // precomputed intra-warp ldmatrix offsets
    const int a_row = wm * 32 + (lane & 15);            // + mi*16
    const int a_colb = (lane >> 4) * 16;                // + ks*32  (bytes)
    const int b_row = wn * 64 + (lane & 7) + ((lane >> 4) << 3);  // + np*16
    const int b_colb = ((lane >> 3) & 1) * 16;          // + ks*32  (bytes)

    for (int c = 0; c < chunks; c++) {
        CP_WAIT1();
        __syncthreads();
        uint32_t sa = sbase + (c % STAGES) * STAGE_BYTES;
        uint32_t sb = sa + TILE_BYTES;

        #pragma unroll
        for (int ks = 0; ks < 2; ks++) {
            uint32_t a[2][4], b[8][2];
            #pragma unroll
            for (int mi = 0; mi < 2; mi++)
                ldsm4(a[mi][0], a[mi][1], a[mi][2], a[mi][3],
                      sa + (a_row + mi * 16) * ROWB + ks * 32 + a_colb);
            #pragma unroll
            for (int np = 0; np < 4; np++) {
                uint32_t r0, r1, r2, r3;
                ldsm4(r0, r1, r2, r3,
                      sb + (b_row + np * 16) * ROWB + ks * 32 + b_colb);
                b[np * 2 + 0][0] = r0; b[np * 2 + 0][1] = r1;
                b[np * 2 + 1][0] = r2; b[np * 2 + 1][1] = r3;
            }
            #pragma unroll
            for (int mi = 0; mi < 2; mi++)
                #pragma unroll
                for (int ni = 0; ni < 8; ni++)
                    mma16816(acc[mi][ni], a[mi], b[ni]);
        }
        __syncthreads();
        if (c + STAGES - 1 < chunks)
            load_tile((c + STAGES - 1) % STAGES, c + STAGES - 1);
    }

    // epilogue
    const int r0 = bm * 128 + wm * 32 + (lane >> 2);
    const int c0 = bn * 128 + wn * 64 + (lane & 3) * 2;
    #pragma unroll
    for (int mi = 0; mi < 2; mi++) {
        #pragma unroll
        for (int ni = 0; ni < 8; ni++) {
            int col = c0 + ni * 8;
            float bx = 0.f, by = 0.f;
            if (bias) { bx = bias[col]; by = bias[col + 1]; }
            float* p0 = C + (size_t)(r0 + mi * 16) * N + col;
            float* p1 = C + (size_t)(r0 + mi * 16 + 8) * N + col;
            *(float2*)p0 = make_float2(acc[mi][ni][0] + bx, acc[mi][ni][1] + by);
            *(float2*)p1 = make_float2(acc[mi][ni][2] + bx, acc[mi][ni][3] + by);
        }
    }
}

// ================= split / transpose-split conversions =================
__global__ void k_split(const float* __restrict__ x, __nv_bfloat16* __restrict__ hi,
                        __nv_bfloat16* __restrict__ lo, int n) {
    int i = blockIdx.x * blockDim.x + threadIdx.x;
    if (i < n) {
        float v = x[i];
        __nv_bfloat16 h = __float2bfloat16(v);
        hi[i] = h;
        lo[i] = __float2bfloat16(v - __bfloat162float(h));
    }
}
// w[K][N] fp32 -> out[N][K] bf16 hi/lo
__global__ void k_split_t(const float* __restrict__ w, __nv_bfloat16* __restrict__ hi,
                          __nv_bfloat16* __restrict__ lo, int K, int N) {
    int i = blockIdx.x * blockDim.x + threadIdx.x;
    if (i < K * N) {
        int k = i / N, n = i - k * N;
        float v = w[i];
        __nv_bfloat16 h = __float2bfloat16(v);
        hi[(size_t)n * K + k] = h;
        lo[(size_t)n * K + k] = __float2bfloat16(v - __bfloat162float(h));
    }
}

// ================= non-GEMM kernels (verified in R1) =================
__global__ void k_zero(float4* __restrict__ p, int n4) {
    int i = blockIdx.x * blockDim.x + threadIdx.x;
    if (i < n4) p[i] = make_float4(0.f, 0.f, 0.f, 0.f);
}

__global__ void k_segsum(const int* __restrict__ tok, const int* __restrict__ seg,
                         const float* __restrict__ emb, float* __restrict__ out) {
    int bt = blockIdx.x;
    int b = bt / T_;
    int t = tok[bt];
    int s = seg[bt];
    const float4* src = (const float4*)(emb + (size_t)t * D_);
    float* dst = out + ((size_t)b * N_ + s) * D_;
    int d = threadIdx.x;
    float4 v = src[d];
    atomicAdd(dst + d * 4 + 0, v.x);
    atomicAdd(dst + d * 4 + 1, v.y);
    atomicAdd(dst + d * 4 + 2, v.z);
    atomicAdd(dst + d * 4 + 3, v.w);
}

__global__ void k_fused(const int* __restrict__ types, const int* __restrict__ lens,
                        const float* __restrict__ table, const float* __restrict__ tsum,
                        float* __restrict__ fused) {
    int bn = blockIdx.x;
    float inv = 1.0f / (float)lens[bn];
    const float* tt = table + (size_t)types[bn] * TD_;
    const float* ts = tsum + (size_t)bn * D_;
    float* o = fused + (size_t)bn * F_;
    int tid = threadIdx.x;
    if (tid < TD_) o[tid] = tt[tid];
    #pragma unroll
    for (int d = tid; d < D_; d += 256) o[TD_ + d] = ts[d] * inv;
}

__global__ void k_scatter(const int* __restrict__ esrc, const int* __restrict__ edst,
                          const float* __restrict__ ew, const float* __restrict__ msg,
                          float* __restrict__ agg) {
    int be = blockIdx.x;
    int b = be / E_;
    int s = esrc[be];
    int t = edst[be];
    float w = ew[be];
    const float4* mp = (const float4*)(msg + ((size_t)b * N_ + s) * D_);
    float* ap = agg + ((size_t)b * N_ + t) * D_;
    int d = threadIdx.x;
    float4 v = mp[d];
    atomicAdd(ap + d * 4 + 0, v.x * w);
    atomicAdd(ap + d * 4 + 1, v.y * w);
    atomicAdd(ap + d * 4 + 2, v.z * w);
    atomicAdd(ap + d * 4 + 3, v.w * w);
}

__global__ void k_gru(const float* __restrict__ gi, const float* __restrict__ gh,
                      float* __restrict__ h) {
    int row = blockIdx.x;
    const float* gip = gi + (size_t)row * G_;
    const float* ghp = gh + (size_t)row * G_;
    float* hp = h + (size_t)row * D_;
    #pragma unroll
    for (int d = threadIdx.x; d < D_; d += 256) {
        float ir = gip[d], iz = gip[D_ + d], in = gip[2 * D_ + d];
        float hr = ghp[d], hz = ghp[D_ + d], hn = ghp[2 * D_ + d];
        float r = 1.0f / (1.0f + expf(-(ir + hr)));
        float z = 1.0f / (1.0f + expf(-(iz + hz)));
        float n = tanhf(in + r * hn);
        hp[d] = (1.0f - z) * n + z * hp[d];
    }
}

__global__ void k_out(const float* __restrict__ h, const int* __restrict__ keep,
                      float* __restrict__ out) {
    int bw = blockIdx.x;
    int b = bw >> 9;
    int wn = bw & 511;
    int kp = keep[b]; if (kp > 512) kp = 512;
    bool valid = wn < kp;
    const float4* hp = (const float4*)(h + (size_t)bw * D_);
    float4* op = (float4*)(out + (size_t)bw * D_);
    int d = threadIdx.x;
    float4 v = valid ? hp[d] : make_float4(0.f, 0.f, 0.f, 0.f);
    op[d] = v;
}

// ================= launch =================
extern "C" void kernel_launch(void* const* d_in, const int* in_sizes, int n_in,
                              void* d_out, int out_size) {
    const int*   node_types = (const int*)d_in[0];
    const int*   tok_ids    = (const int*)d_in[1];
    const int*   seg_ids    = (const int*)d_in[2];
    const int*   tok_lens   = (const int*)d_in[3];
    const int*   gnode_lens = (const int*)d_in[4];
    const int*   esrc       = (const int*)d_in[5];
    const int*   edst       = (const int*)d_in[6];
    const float* ew         = (const float*)d_in[7];
    const float* type_table = (const float*)d_in[8];
    const float* word_emb   = (const float*)d_in[9];
    const float* fusion_w   = (const float*)d_in[10];
    const float* fusion_b   = (const float*)d_in[11];
    const float* ggnn_w     = (const float*)d_in[12];
    const float* w_ih       = (const float*)d_in[13];
    const float* w_hh       = (const float*)d_in[14];
    const float* b_ih       = (const float*)d_in[15];
    const float* b_hh       = (const float*)d_in[16];
    float* out = (float*)d_out;

    cudaFuncSetAttribute(bmma, cudaFuncAttributeMaxDynamicSharedMemorySize, SMEM_SZ);

    float *text, *fused, *h, *msg, *agg, *gi, *gh;
    cudaGetSymbolAddress((void**)&text,  g_text);
    cudaGetSymbolAddress((void**)&fused, g_fused);
    cudaGetSymbolAddress((void**)&h,     g_h);
    cudaGetSymbolAddress((void**)&msg,   g_msg);
    cudaGetSymbolAddress((void**)&agg,   g_agg);
    cudaGetSymbolAddress((void**)&gi,    g_gi);
    cudaGetSymbolAddress((void**)&gh,    g_gh);

    __nv_bfloat16 *f_hi, *f_lo, *h_hi, *h_lo, *a_hi, *a_lo;
    __nv_bfloat16 *fw_hi, *fw_lo, *gw_hi, *gw_lo, *ih_hi, *ih_lo, *hh_hi, *hh_lo;
    cudaGetSymbolAddress((void**)&f_hi,  s_f_hi);
    cudaGetSymbolAddress((void**)&f_lo,  s_f_lo);
    cudaGetSymbolAddress((void**)&h_hi,  s_h_hi);
    cudaGetSymbolAddress((void**)&h_lo,  s_h_lo);
    cudaGetSymbolAddress((void**)&a_hi,  s_a_hi);
    cudaGetSymbolAddress((void**)&a_lo,  s_a_lo);
    cudaGetSymbolAddress((void**)&fw_hi, s_fw_hi);
    cudaGetSymbolAddress((void**)&fw_lo, s_fw_lo);
    cudaGetSymbolAddress((void**)&gw_hi, s_gw_hi);
    cudaGetSymbolAddress((void**)&gw_lo, s_gw_lo);
    cudaGetSymbolAddress((void**)&ih_hi, s_ih_hi);
    cudaGetSymbolAddress((void**)&ih_lo, s_ih_lo);
    cudaGetSymbolAddress((void**)&hh_hi, s_hh_hi);
    cudaGetSymbolAddress((void**)&hh_lo, s_hh_lo);

    const int n4 = M_ * D_ / 4;

    // --- weight conversions ---
    k_split_t<<<(F_ * D_ + 255) / 256, 256>>>(fusion_w, fw_hi, fw_lo, F_, D_);
    for (int l = 0; l < L_; l++)
        k_split_t<<<(D_ * D_ + 255) / 256, 256>>>(
            ggnn_w + (size_t)l * D_ * D_, gw_hi + (size_t)l * D_ * D_,
            gw_lo + (size_t)l * D_ * D_, D_, D_);
    k_split<<<(G_ * D_ + 255) / 256, 256>>>(w_ih, ih_hi, ih_lo, G_ * D_);
    k_split<<<(G_ * D_ + 255) / 256, 256>>>(w_hh, hh_hi, hh_lo, G_ * D_);

    // --- embeddings + segment mean + fusion input ---
    k_zero<<<(n4 + 255) / 256, 256>>>((float4*)text, n4);
    k_segsum<<<B_ * T_, 192>>>(tok_ids, seg_ids, word_emb, text);
    k_fused<<<M_, 256>>>(node_types, tok_lens, type_table, text, fused);
    k_split<<<(M_ * F_ + 255) / 256, 256>>>(fused, f_hi, f_lo, M_ * F_);

    // h = fused @ fusion_w + fusion_b   [4096,896]x[896,768]
    bmma<<<dim3(D_ / 128, M_ / 128), 256, SMEM_SZ>>>(f_hi, f_lo, fw_hi, fw_lo,
                                                      fusion_b, h, D_, F_);
    k_split<<<(M_ * D_ + 255) / 256, 256>>>(h, h_hi, h_lo, M_ * D_);

    for (int l = 0; l < L_; ++l) {
        // msg = h @ ggnn_w[l]
        bmma<<<dim3(D_ / 128, M_ / 128), 256, SMEM_SZ>>>(
            h_hi, h_lo, gw_hi + (size_t)l * D_ * D_, gw_lo + (size_t)l * D_ * D_,
            nullptr, msg, D_, D_);
        // agg = scatter_add(msg[src] * w -> dst)
        k_zero<<<(n4 + 255) / 256, 256>>>((float4*)agg, n4);
        k_scatter<<<B_ * E_, 192>>>(esrc, edst, ew, msg, agg);
        k_split<<<(M_ * D_ + 255) / 256, 256>>>(agg, a_hi, a_lo, M_ * D_);
        // gi = agg @ w_ih^T + b_ih ; gh = h @ w_hh^T + b_hh
        bmma<<<dim3(G_ / 128, M_ / 128), 256, SMEM_SZ>>>(a_hi, a_lo, ih_hi, ih_lo,
                                                          b_ih, gi, G_, D_);
        bmma<<<dim3(G_ / 128, M_ / 128), 256, SMEM_SZ>>>(h_hi, h_lo, hh_hi, hh_lo,
                                                          b_hh, gh, G_, D_);
        // GRU update (in place on h), then re-split h for next layer
        k_gru<<<M_, 256>>>(gi, gh, h);
        k_split<<<(M_ * D_ + 255) / 256, 256>>>(h, h_hi, h_lo, M_ * D_);
    }

    k_out<<<M_, 192>>>(h, gnode_lens, out);
}

// round 4
// speedup vs baseline: 1.7526x; 1.0825x over previous
#include <cuda_runtime.h>
#include <cuda_bf16.h>
#include <cstdint>
#include <cstddef>

#define B_ 8
#define N_ 512
#define T_ 2048
#define E_ 4096
#define D_ 768
#define TD_ 128
#define L_ 4
#define F_ (TD_ + D_)   /* 896 */
#define G_ (3 * D_)     /* 2304 */
#define M_ (B_ * N_)    /* 4096 */
#define TPN_ (T_ / N_)  /* 4 tokens per node */

// ---------------- fp32 scratch ----------------
__device__ float g_fused[M_ * F_];
__device__ float g_h    [M_ * D_];
__device__ float g_msg  [M_ * D_];
__device__ float g_agg  [M_ * D_];
__device__ float g_gi   [M_ * G_];
__device__ float g_gh   [M_ * G_];

// ---------------- bf16 split weights ----------------
__device__ __nv_bfloat16 s_fw_hi[D_ * F_];      // fusion_w^T  [768][896]
__device__ __nv_bfloat16 s_fw_lo[D_ * F_];
__device__ __nv_bfloat16 s_gw_hi[L_ * D_ * D_]; // ggnn_w[l]^T [768][768]
__device__ __nv_bfloat16 s_gw_lo[L_ * D_ * D_];
__device__ __nv_bfloat16 s_ih_hi[G_ * D_];      // w_ih [2304][768]
__device__ __nv_bfloat16 s_ih_lo[G_ * D_];
__device__ __nv_bfloat16 s_hh_hi[G_ * D_];
__device__ __nv_bfloat16 s_hh_lo[G_ * D_];

// ================= helpers =================
__device__ __forceinline__ uint32_t smem_u32(const void* p) {
    uint32_t a;
    asm("{ .reg .u64 t; cvta.to.shared.u64 t, %1; cvt.u32.u64 %0, t; }" : "=r"(a) : "l"(p));
    return a;
}
__device__ __forceinline__ void cp16(uint32_t saddr, const void* g) {
    asm volatile("cp.async.cg.shared.global [%0], [%1], 16;" :: "r"(saddr), "l"(g) : "memory");
}
#define CP_COMMIT() asm volatile("cp.async.commit_group;" ::: "memory")
#define CP_WAIT1()  asm volatile("cp.async.wait_group 1;" ::: "memory")

__device__ __forceinline__ void ldsm4(uint32_t& r0, uint32_t& r1, uint32_t& r2,
                                      uint32_t& r3, uint32_t a) {
    asm volatile("ldmatrix.sync.aligned.m8n8.x4.shared.b16 {%0,%1,%2,%3}, [%4];"
                 : "=r"(r0), "=r"(r1), "=r"(r2), "=r"(r3) : "r"(a));
}
__device__ __forceinline__ void mma16816(float* d, const uint32_t* a, const uint32_t* b) {
    asm volatile(
        "mma.sync.aligned.m16n8k16.row.col.f32.bf16.bf16.f32 "
        "{%0,%1,%2,%3}, {%4,%5,%6,%7}, {%8,%9}, {%0,%1,%2,%3};"
        : "+f"(d[0]), "+f"(d[1]), "+f"(d[2]), "+f"(d[3])
        : "r"(a[0]), "r"(a[1]), "r"(a[2]), "r"(a[3]), "r"(b[0]), "r"(b[1]));
}

// 8 fp32 -> 4x bf16x2 hi + 4x bf16x2 lo (packed)
__device__ __forceinline__ void cvt8(float4 f0, float4 f1, uint4& H, uint4& Lo) {
    __nv_bfloat162 h0 = __floats2bfloat162_rn(f0.x, f0.y);
    __nv_bfloat162 h1 = __floats2bfloat162_rn(f0.z, f0.w);
    __nv_bfloat162 h2 = __floats2bfloat162_rn(f1.x, f1.y);
    __nv_bfloat162 h3 = __floats2bfloat162_rn(f1.z, f1.w);
    __nv_bfloat162 l0 = __floats2bfloat162_rn(f0.x - __bfloat162float(h0.x), f0.y - __bfloat162float(h0.y));
    __nv_bfloat162 l1 = __floats2bfloat162_rn(f0.z - __bfloat162float(h1.x), f0.w - __bfloat162float(h1.y));
    __nv_bfloat162 l2 = __floats2bfloat162_rn(f1.x - __bfloat162float(h2.x), f1.y - __bfloat162float(h2.y));
    __nv_bfloat162 l3 = __floats2bfloat162_rn(f1.z - __bfloat162float(h3.x), f1.w - __bfloat162float(h3.y));
    H.x  = *(uint32_t*)&h0; H.y  = *(uint32_t*)&h1; H.z  = *(uint32_t*)&h2; H.w  = *(uint32_t*)&h3;
    Lo.x = *(uint32_t*)&l0; Lo.y = *(uint32_t*)&l1; Lo.z = *(uint32_t*)&l2; Lo.w = *(uint32_t*)&l3;
}

// smem tile: 128 rows x 32 bf16 (64B) + 16B pad -> 80B row stride
#define ROWB    80
#define TILEB   (128 * ROWB)          /* 10240 */
#define STAGEB  (4 * TILEB)           /* Ahi,Alo,Bhi,Blo = 40960 */
#define STAGES  3
#define SMEM_SZ (STAGES * STAGEB)     /* 122880 */

// ================= mma.sync split-bf16 GEMM, fp32 A with on-the-fly split ====
// C[M,N] = A[M,K](fp32) @ (Bhi+Blo)[N,K]^T via 3-term (AhiBhi + AhiBlo + AloBhi)
// grid=(N/128, M/128), block=256, dyn smem = SMEM_SZ. K%32==0, N%128==0.
__global__ void __launch_bounds__(256) bmma(
    const float* __restrict__ A,
    const __nv_bfloat16* __restrict__ Bhi, const __nv_bfloat16* __restrict__ Blo,
    const float* __restrict__ bias, float* __restrict__ C, int N, int K)
{
    extern __shared__ char smem[];
    const uint32_t sbase = smem_u32(smem);
    const int tid = threadIdx.x;
    const int wid = tid >> 5, lane = tid & 31;
    const int wm = wid & 3, wn = wid >> 2;           // 4x2 warp grid
    const int bn = blockIdx.x, bm = blockIdx.y;

    const int nkc = K >> 5;

    // B loader lanes (cp.async, 16B each)
    const int lrow0 = tid >> 2;
    const int lrow1 = 64 + (tid >> 2);
    const int lseg  = tid & 3;
    // A loader lanes (fp32 LDG + convert + STS)
    const int ar = tid >> 1;          // row 0..127
    const int asg = tid & 1;          // 16-float half

    auto load_stage = [&](int stage, int kc) {
        uint32_t sb = sbase + stage * STAGEB;
        int kof = kc * 32;
        // B hi/lo via cp.async
        cp16(sb + 2 * TILEB + lrow0 * ROWB + lseg * 16,
             Bhi + (size_t)(bn * 128 + lrow0) * K + kof + lseg * 8);
        cp16(sb + 2 * TILEB + lrow1 * ROWB + lseg * 16,
             Bhi + (size_t)(bn * 128 + lrow1) * K + kof + lseg * 8);
        cp16(sb + 3 * TILEB + lrow0 * ROWB + lseg * 16,
             Blo + (size_t)(bn * 128 + lrow0) * K + kof + lseg * 8);
        cp16(sb + 3 * TILEB + lrow1 * ROWB + lseg * 16,
             Blo + (size_t)(bn * 128 + lrow1) * K + kof + lseg * 8);
        CP_COMMIT();
        // A fp32 -> hi/lo tiles
        const float4* Ap = (const float4*)(A + (size_t)(bm * 128 + ar) * K + kof + asg * 16);
        float4 f0 = Ap[0], f1 = Ap[1], f2 = Ap[2], f3 = Ap[3];
        uint4 H0, L0, H1, L1;
        cvt8(f0, f1, H0, L0);
        cvt8(f2, f3, H1, L1);
        char* arow = smem + stage * STAGEB + ar * ROWB + asg * 32;
        *(uint4*)(arow)              = H0;
        *(uint4*)(arow + 16)         = H1;
        *(uint4*)(arow + TILEB)      = L0;
        *(uint4*)(arow + TILEB + 16) = L1;
    };

    float acc[2][8][4];
    #pragma unroll
    for (int i = 0; i < 2; i++)
        #pragma unroll
        for (int j = 0; j < 8; j++)
            #pragma unroll
            for (int q = 0; q < 4; q++) acc[i][j][q] = 0.f;

    load_stage(0, 0);
    load_stage(1, 1);

    const int a_row  = wm * 32 + (lane & 15);
    const int a_colb = (lane >> 4) * 16;
    const int b_row  = wn * 64 + (lane & 7) + ((lane >> 4) << 3);
    const int b_colb = ((lane >> 3) & 1) * 16;

    for (int kc = 0; kc < nkc; kc++) {
        CP_WAIT1();
        __syncthreads();
        uint32_t st = sbase + (kc % STAGES) * STAGEB;
        uint32_t sah = st, sal = st + TILEB, sbh = st + 2 * TILEB, sbl = st + 3 * TILEB;

        #pragma unroll
        for (int ks = 0; ks < 2; ks++) {
            uint32_t ah[2][4], al[2][4], bh[8][2], bl[8][2];
            #pragma unroll
            for (int mi = 0; mi < 2; mi++)
                ldsm4(ah[mi][0], ah[mi][1], ah[mi][2], ah[mi][3],
                      sah + (a_row + mi * 16) * ROWB + ks * 32 + a_colb);
            #pragma unroll
            for (int np = 0; np < 4; np++) {
                uint32_t r0, r1, r2, r3;
                ldsm4(r0, r1, r2, r3, sbh + (b_row + np * 16) * ROWB + ks * 32 + b_colb);
                bh[np * 2 + 0][0] = r0; bh[np * 2 + 0][1] = r1;
                bh[np * 2 + 1][0] = r2; bh[np * 2 + 1][1] = r3;
            }
            // term 0: Ahi * Bhi
            #pragma unroll
            for (int mi = 0; mi < 2; mi++)
                #pragma unroll
                for (int ni = 0; ni < 8; ni++)
                    mma16816(acc[mi][ni], ah[mi], bh[ni]);
            #pragma unroll
            for (int np = 0; np < 4; np++) {
                uint32_t r0, r1, r2, r3;
                ldsm4(r0, r1, r2, r3, sbl + (b_row + np * 16) * ROWB + ks * 32 + b_colb);
                bl[np * 2 + 0][0] = r0; bl[np * 2 + 0][1] = r1;
                bl[np * 2 + 1][0] = r2; bl[np * 2 + 1][1] = r3;
            }
            // term 1: Ahi * Blo
            #pragma unroll
            for (int mi = 0; mi < 2; mi++)
                #pragma unroll
                for (int ni = 0; ni < 8; ni++)
                    mma16816(acc[mi][ni], ah[mi], bl[ni]);
            #pragma unroll
            for (int mi = 0; mi < 2; mi++)
                ldsm4(al[mi][0], al[mi][1], al[mi][2], al[mi][3],
                      sal + (a_row + mi * 16) * ROWB + ks * 32 + a_colb);
            // term 2: Alo * Bhi
            #pragma unroll
            for (int mi = 0; mi < 2; mi++)
                #pragma unroll
                for (int ni = 0; ni < 8; ni++)
                    mma16816(acc[mi][ni], al[mi], bh[ni]);
        }
        __syncthreads();
        if (kc + 2 < nkc) load_stage((kc + 2) % STAGES, kc + 2);
    }

    // epilogue
    const int r0 = bm * 128 + wm * 32 + (lane >> 2);
    const int c0 = bn * 128 + wn * 64 + (lane & 3) * 2;
    #pragma unroll
    for (int mi = 0; mi < 2; mi++) {
        #pragma unroll
        for (int ni = 0; ni < 8; ni++) {
            int col = c0 + ni * 8;
            float bx = 0.f, by = 0.f;
            if (bias) { bx = bias[col]; by = bias[col + 1]; }
            float* p0 = C + (size_t)(r0 + mi * 16) * N + col;
            float* p1 = C + (size_t)(r0 + mi * 16 + 8) * N + col;
            *(float2*)p0 = make_float2(acc[mi][ni][0] + bx, acc[mi][ni][1] + by);
            *(float2*)p1 = make_float2(acc[mi][ni][2] + bx, acc[mi][ni][3] + by);
        }
    }
}

// ================= weight split conversions =================
__global__ void k_split(const float* __restrict__ x, __nv_bfloat16* __restrict__ hi,
                        __nv_bfloat16* __restrict__ lo, int n) {
    int i = blockIdx.x * blockDim.x + threadIdx.x;
    if (i < n) {
        float v = x[i];
        __nv_bfloat16 h = __float2bfloat16(v);
        hi[i] = h;
        lo[i] = __float2bfloat16(v - __bfloat162float(h));
    }
}
// w[K][N] fp32 -> out[N][K] bf16 hi/lo
__global__ void k_split_t(const float* __restrict__ w, __nv_bfloat16* __restrict__ hi,
                          __nv_bfloat16* __restrict__ lo, int K, int N) {
    int i = blockIdx.x * blockDim.x + threadIdx.x;
    if (i < K * N) {
        int k = i / N, n = i - k * N;
        float v = w[i];
        __nv_bfloat16 h = __float2bfloat16(v);
        hi[(size_t)n * K + k] = h;
        lo[(size_t)n * K + k] = __float2bfloat16(v - __bfloat162float(h));
    }
}
// batched per-layer transpose split for ggnn_w [L][D][D]
__global__ void k_split_tb(const float* __restrict__ w, __nv_bfloat16* __restrict__ hi,
                           __nv_bfloat16* __restrict__ lo) {
    int i = blockIdx.x * blockDim.x + threadIdx.x;
    if (i < L_ * D_ * D_) {
        int l = i / (D_ * D_), r = i - l * (D_ * D_);
        int k = r / D_, n = r - k * D_;
        float v = w[i];
        __nv_bfloat16 h = __float2bfloat16(v);
        size_t o = (size_t)l * D_ * D_ + (size_t)n * D_ + k;
        hi[o] = h;
        lo[o] = __float2bfloat16(v - __bfloat162float(h));
    }
}

// ================= embed: type gather + contiguous 4-token mean -> fused =====
__global__ void k_embed(const int* __restrict__ types, const int* __restrict__ tok,
                        const int* __restrict__ lens, const float* __restrict__ table,
                        const float* __restrict__ emb, float* __restrict__ fused) {
    int bn = blockIdx.x;               // b*N + n
    int b = bn >> 9, n = bn & 511;
    int base = b * T_ + n * TPN_;
    int t0 = tok[base], t1 = tok[base + 1], t2 = tok[base + 2], t3 = tok[base + 3];
    float inv = 1.0f / (float)lens[bn];
    float* o = fused + (size_t)bn * F_;
    int d = threadIdx.x;               // 192
    if (d < TD_ / 4)
        ((float4*)o)[d] = ((const float4*)(table + (size_t)types[bn] * TD_))[d];
    float4 e0 = ((const float4*)(emb + (size_t)t0 * D_))[d];
    float4 e1 = ((const float4*)(emb + (size_t)t1 * D_))[d];
    float4 e2 = ((const float4*)(emb + (size_t)t2 * D_))[d];
    float4 e3 = ((const float4*)(emb + (size_t)t3 * D_))[d];
    float4 s;
    s.x = (e0.x + e1.x + e2.x + e3.x) * inv;
    s.y = (e0.y + e1.y + e2.y + e3.y) * inv;
    s.z = (e0.z + e1.z + e2.z + e3.z) * inv;
    s.w = (e0.w + e1.w + e2.w + e3.w) * inv;
    ((float4*)(o + TD_))[d] = s;
}

// ================= misc kernels =================
__global__ void k_zero(float4* __restrict__ p, int n4) {
    int i = blockIdx.x * blockDim.x + threadIdx.x;
    if (i < n4) p[i] = make_float4(0.f, 0.f, 0.f, 0.f);
}

__global__ void k_scatter(const int* __restrict__ esrc, const int* __restrict__ edst,
                          const float* __restrict__ ew, const float* __restrict__ msg,
                          float* __restrict__ agg) {
    int be = blockIdx.x;
    int b = be / E_;
    int s = esrc[be];
    int t = edst[be];
    float w = ew[be];
    const float4* mp = (const float4*)(msg + ((size_t)b * N_ + s) * D_);
    float* ap = agg + ((size_t)b * N_ + t) * D_;
    int d = threadIdx.x;               // 192
    float4 v = mp[d];
    asm volatile("red.global.add.v4.f32 [%0], {%1, %2, %3, %4};"
                 :: "l"(ap + d * 4), "f"(v.x * w), "f"(v.y * w),
                    "f"(v.z * w), "f"(v.w * w) : "memory");
}

__global__ void k_gru(const float* __restrict__ gi, const float* __restrict__ gh,
                      float* __restrict__ h) {
    int row = blockIdx.x;
    const float* gip = gi + (size_t)row * G_;
    const float* ghp = gh + (size_t)row * G_;
    float* hp = h + (size_t)row * D_;
    #pragma unroll
    for (int d = threadIdx.x; d < D_; d += 256) {
        float ir = gip[d], iz = gip[D_ + d], in = gip[2 * D_ + d];
        float hr = ghp[d], hz = ghp[D_ + d], hn = ghp[2 * D_ + d];
        float r = 1.0f / (1.0f + expf(-(ir + hr)));
        float z = 1.0f / (1.0f + expf(-(iz + hz)));
        float n = tanhf(in + r * hn);
        hp[d] = (1.0f - z) * n + z * hp[d];
    }
}

__global__ void k_out(const float* __restrict__ h, const int* __restrict__ keep,
                      float* __restrict__ out) {
    int bw = blockIdx.x;
    int b = bw >> 9;
    int wn = bw & 511;
    int kp = keep[b]; if (kp > 512) kp = 512;
    bool valid = wn < kp;
    const float4* hp = (const float4*)(h + (size_t)bw * D_);
    float4* op = (float4*)(out + (size_t)bw * D_);
    int d = threadIdx.x;
    float4 v = valid ? hp[d] : make_float4(0.f, 0.f, 0.f, 0.f);
    op[d] = v;
}

// ================= launch =================
extern "C" void kernel_launch(void* const* d_in, const int* in_sizes, int n_in,
                              void* d_out, int out_size) {
    const int*   node_types = (const int*)d_in[0];
    const int*   tok_ids    = (const int*)d_in[1];
    const int*   seg_ids    = (const int*)d_in[2]; (void)seg_ids;
    const int*   tok_lens   = (const int*)d_in[3];
    const int*   gnode_lens = (const int*)d_in[4];
    const int*   esrc       = (const int*)d_in[5];
    const int*   edst       = (const int*)d_in[6];
    const float* ew         = (const float*)d_in[7];
    const float* type_table = (const float*)d_in[8];
    const float* word_emb   = (const float*)d_in[9];
    const float* fusion_w   = (const float*)d_in[10];
    const float* fusion_b   = (const float*)d_in[11];
    const float* ggnn_w     = (const float*)d_in[12];
    const float* w_ih       = (const float*)d_in[13];
    const float* w_hh       = (const float*)d_in[14];
    const float* b_ih       = (const float*)d_in[15];
    const float* b_hh       = (const float*)d_in[16];
    float* out = (float*)d_out;

    cudaFuncSetAttribute(bmma, cudaFuncAttributeMaxDynamicSharedMemorySize, SMEM_SZ);

    float *fused, *h, *msg, *agg, *gi, *gh;
    cudaGetSymbolAddress((void**)&fused, g_fused);
    cudaGetSymbolAddress((void**)&h,     g_h);
    cudaGetSymbolAddress((void**)&msg,   g_msg);
    cudaGetSymbolAddress((void**)&agg,   g_agg);
    cudaGetSymbolAddress((void**)&gi,    g_gi);
    cudaGetSymbolAddress((void**)&gh,    g_gh);

    __nv_bfloat16 *fw_hi, *fw_lo, *gw_hi, *gw_lo, *ih_hi, *ih_lo, *hh_hi, *hh_lo;
    cudaGetSymbolAddress((void**)&fw_hi, s_fw_hi);
    cudaGetSymbolAddress((void**)&fw_lo, s_fw_lo);
    cudaGetSymbolAddress((void**)&gw_hi, s_gw_hi);
    cudaGetSymbolAddress((void**)&gw_lo, s_gw_lo);
    cudaGetSymbolAddress((void**)&ih_hi, s_ih_hi);
    cudaGetSymbolAddress((void**)&ih_lo, s_ih_lo);
    cudaGetSymbolAddress((void**)&hh_hi, s_hh_hi);
    cudaGetSymbolAddress((void**)&hh_lo, s_hh_lo);

    const int n4 = M_ * D_ / 4;

    // --- weight conversions ---
    k_split_t<<<(F_ * D_ + 255) / 256, 256>>>(fusion_w, fw_hi, fw_lo, F_, D_);
    k_split_tb<<<(L_ * D_ * D_ + 255) / 256, 256>>>(ggnn_w, gw_hi, gw_lo);
    k_split<<<(G_ * D_ + 255) / 256, 256>>>(w_ih, ih_hi, ih_lo, G_ * D_);
    k_split<<<(G_ * D_ + 255) / 256, 256>>>(w_hh, hh_hi, hh_lo, G_ * D_);

    // --- embeddings + mean + fusion input (single gather kernel) ---
    k_embed<<<M_, 192>>>(node_types, tok_ids, tok_lens, type_table, word_emb, fused);

    // h = fused @ fusion_w + fusion_b   [4096,896]x[896,768]
    bmma<<<dim3(D_ / 128, M_ / 128), 256, SMEM_SZ>>>(fused, fw_hi, fw_lo,
                                                      fusion_b, h, D_, F_);

    for (int l = 0; l < L_; ++l) {
        // msg = h @ ggnn_w[l]
        bmma<<<dim3(D_ / 128, M_ / 128), 256, SMEM_SZ>>>(
            h, gw_hi + (size_t)l * D_ * D_, gw_lo + (size_t)l * D_ * D_,
            nullptr, msg, D_, D_);
        // agg = scatter_add(msg[src] * w -> dst)
        k_zero<<<(n4 + 255) / 256, 256>>>((float4*)agg, n4);
        k_scatter<<<B_ * E_, 192>>>(esrc, edst, ew, msg, agg);
        // gi = agg @ w_ih^T + b_ih ; gh = h @ w_hh^T + b_hh
        bmma<<<dim3(G_ / 128, M_ / 128), 256, SMEM_SZ>>>(agg, ih_hi, ih_lo,
                                                          b_ih, gi, G_, D_);
        bmma<<<dim3(G_ / 128, M_ / 128), 256, SMEM_SZ>>>(h, hh_hi, hh_lo,
                                                          b_hh, gh, G_, D_);
        // GRU update (in place on h)
        k_gru<<<M_, 256>>>(gi, gh, h);
    }

    k_out<<<M_, 192>>>(h, gnode_lens, out);
}

// round 5
// speedup vs baseline: 2.7844x; 1.5888x over previous
#include <cuda_runtime.h>
#include <cuda_fp16.h>
#include <cstdint>
#include <cstddef>

#define B_ 8
#define N_ 512
#define T_ 2048
#define E_ 4096
#define D_ 768
#define TD_ 128
#define L_ 4
#define F_ (TD_ + D_)   /* 896 */
#define G_ (3 * D_)     /* 2304 */
#define M_ (B_ * N_)    /* 4096 */
#define TPN_ (T_ / N_)  /* 4 tokens per node */

// ---------------- fp32 scratch ----------------
__device__ float g_fused[M_ * F_];
__device__ float g_h    [M_ * D_];
__device__ float g_msg  [M_ * D_];
__device__ float g_agg  [M_ * D_];
__device__ float g_gi   [M_ * G_];
__device__ float g_gh   [M_ * G_];

// ---------------- fp16 weights (single precision copy, K-major) --------------
__device__ __half s_fw[D_ * F_];        // fusion_w^T  [768][896]
__device__ __half s_gw[L_ * D_ * D_];   // ggnn_w[l]^T [768][768]
__device__ __half s_ih[G_ * D_];        // w_ih [2304][768]
__device__ __half s_hh[G_ * D_];

// ================= helpers =================
__device__ __forceinline__ uint32_t smem_u32(const void* p) {
    uint32_t a;
    asm("{ .reg .u64 t; cvta.to.shared.u64 t, %1; cvt.u32.u64 %0, t; }" : "=r"(a) : "l"(p));
    return a;
}
__device__ __forceinline__ void cp16(uint32_t saddr, const void* g) {
    asm volatile("cp.async.cg.shared.global [%0], [%1], 16;" :: "r"(saddr), "l"(g) : "memory");
}
#define CP_COMMIT() asm volatile("cp.async.commit_group;" ::: "memory")
#define CP_WAIT1()  asm volatile("cp.async.wait_group 1;" ::: "memory")

__device__ __forceinline__ void ldsm4(uint32_t& r0, uint32_t& r1, uint32_t& r2,
                                      uint32_t& r3, uint32_t a) {
    asm volatile("ldmatrix.sync.aligned.m8n8.x4.shared.b16 {%0,%1,%2,%3}, [%4];"
                 : "=r"(r0), "=r"(r1), "=r"(r2), "=r"(r3) : "r"(a));
}
__device__ __forceinline__ void mma16816(float* d, const uint32_t* a, const uint32_t* b) {
    asm volatile(
        "mma.sync.aligned.m16n8k16.row.col.f32.f16.f16.f32 "
        "{%0,%1,%2,%3}, {%4,%5,%6,%7}, {%8,%9}, {%0,%1,%2,%3};"
        : "+f"(d[0]), "+f"(d[1]), "+f"(d[2]), "+f"(d[3])
        : "r"(a[0]), "r"(a[1]), "r"(a[2]), "r"(a[3]), "r"(b[0]), "r"(b[1]));
}

// 8 fp32 -> 4x half2 hi + 4x half2 lo (packed)
__device__ __forceinline__ void cvt8(float4 f0, float4 f1, uint4& H, uint4& Lo) {
    __half2 h0 = __floats2half2_rn(f0.x, f0.y);
    __half2 h1 = __floats2half2_rn(f0.z, f0.w);
    __half2 h2 = __floats2half2_rn(f1.x, f1.y);
    __half2 h3 = __floats2half2_rn(f1.z, f1.w);
    __half2 l0 = __floats2half2_rn(f0.x - __half2float(h0.x), f0.y - __half2float(h0.y));
    __half2 l1 = __floats2half2_rn(f0.z - __half2float(h1.x), f0.w - __half2float(h1.y));
    __half2 l2 = __floats2half2_rn(f1.x - __half2float(h2.x), f1.y - __half2float(h2.y));
    __half2 l3 = __floats2half2_rn(f1.z - __half2float(h3.x), f1.w - __half2float(h3.y));
    H.x  = *(uint32_t*)&h0; H.y  = *(uint32_t*)&h1; H.z  = *(uint32_t*)&h2; H.w  = *(uint32_t*)&h3;
    Lo.x = *(uint32_t*)&l0; Lo.y = *(uint32_t*)&l1; Lo.z = *(uint32_t*)&l2; Lo.w = *(uint32_t*)&l3;
}

// smem tile: 128 rows x 32 halves (64B) + 16B pad -> 80B row stride
#define ROWB    80
#define TILEB   (128 * ROWB)          /* 10240 */
#define STAGEB  (3 * TILEB)           /* Ahi, Alo, B = 30720 */
#define STAGES  3
#define SMEM_SZ (STAGES * STAGEB)     /* 92160 */

// ================= mma.sync 2-term fp16 GEMM, fp32 A split on the fly ========
// C[M,N] = A[M,K](fp32) @ Bh[N,K]^T via (Ahi + Alo) * Bh, fp32 accum, + bias.
// grid=(N/128, M/128), block=256, dyn smem = SMEM_SZ. K%32==0, N%128==0.
__global__ void __launch_bounds__(256) bmma(
    const float* __restrict__ A, const __half* __restrict__ Bh,
    const float* __restrict__ bias, float* __restrict__ C, int N, int K)
{
    extern __shared__ char smem[];
    const uint32_t sbase = smem_u32(smem);
    const int tid = threadIdx.x;
    const int wid = tid >> 5, lane = tid & 31;
    const int wm = wid & 3, wn = wid >> 2;           // 4x2 warp grid
    const int bn = blockIdx.x, bm = blockIdx.y;

    const int nkc = K >> 5;

    // B loader lanes (cp.async, 16B each; 2 per thread covers 128 rows x 64B)
    const int lrow0 = tid >> 2;
    const int lrow1 = 64 + (tid >> 2);
    const int lseg  = tid & 3;
    // A loader lanes (fp32 LDG + convert + STS)
    const int ar = tid >> 1;          // row 0..127
    const int asg = tid & 1;          // 16-float half

    auto load_stage = [&](int stage, int kc) {
        uint32_t sb = sbase + stage * STAGEB;
        int kof = kc * 32;
        // B fp16 via cp.async
        cp16(sb + 2 * TILEB + lrow0 * ROWB + lseg * 16,
             Bh + (size_t)(bn * 128 + lrow0) * K + kof + lseg * 8);
        cp16(sb + 2 * TILEB + lrow1 * ROWB + lseg * 16,
             Bh + (size_t)(bn * 128 + lrow1) * K + kof + lseg * 8);
        CP_COMMIT();
        // A fp32 -> hi/lo fp16 tiles
        const float4* Ap = (const float4*)(A + (size_t)(bm * 128 + ar) * K + kof + asg * 16);
        float4 f0 = Ap[0], f1 = Ap[1], f2 = Ap[2], f3 = Ap[3];
        uint4 H0, L0, H1, L1;
        cvt8(f0, f1, H0, L0);
        cvt8(f2, f3, H1, L1);
        char* arow = smem + stage * STAGEB + ar * ROWB + asg * 32;
        *(uint4*)(arow)              = H0;
        *(uint4*)(arow + 16)         = H1;
        *(uint4*)(arow + TILEB)      = L0;
        *(uint4*)(arow + TILEB + 16) = L1;
    };

    float acc[2][8][4];
    #pragma unroll
    for (int i = 0; i < 2; i++)
        #pragma unroll
        for (int j = 0; j < 8; j++)
            #pragma unroll
            for (int q = 0; q < 4; q++) acc[i][j][q] = 0.f;

    load_stage(0, 0);
    load_stage(1, 1);

    const int a_row  = wm * 32 + (lane & 15);
    const int a_colb = (lane >> 4) * 16;
    const int b_row  = wn * 64 + (lane & 7) + ((lane >> 4) << 3);
    const int b_colb = ((lane >> 3) & 1) * 16;

    for (int kc = 0; kc < nkc; kc++) {
        CP_WAIT1();
        __syncthreads();
        uint32_t st = sbase + (kc % STAGES) * STAGEB;
        uint32_t sah = st, sal = st + TILEB, sbh = st + 2 * TILEB;

        #pragma unroll
        for (int ks = 0; ks < 2; ks++) {
            uint32_t ah[2][4], al[2][4], b[8][2];
            #pragma unroll
            for (int mi = 0; mi < 2; mi++)
                ldsm4(ah[mi][0], ah[mi][1], ah[mi][2], ah[mi][3],
                      sah + (a_row + mi * 16) * ROWB + ks * 32 + a_colb);
            #pragma unroll
            for (int np = 0; np < 4; np++) {
                uint32_t r0, r1, r2, r3;
                ldsm4(r0, r1, r2, r3, sbh + (b_row + np * 16) * ROWB + ks * 32 + b_colb);
                b[np * 2 + 0][0] = r0; b[np * 2 + 0][1] = r1;
                b[np * 2 + 1][0] = r2; b[np * 2 + 1][1] = r3;
            }
            // term 0: Ahi * B
            #pragma unroll
            for (int mi = 0; mi < 2; mi++)
                #pragma unroll
                for (int ni = 0; ni < 8; ni++)
                    mma16816(acc[mi][ni], ah[mi], b[ni]);
            #pragma unroll
            for (int mi = 0; mi < 2; mi++)
                ldsm4(al[mi][0], al[mi][1], al[mi][2], al[mi][3],
                      sal + (a_row + mi * 16) * ROWB + ks * 32 + a_colb);
            // term 1: Alo * B
            #pragma unroll
            for (int mi = 0; mi < 2; mi++)
                #pragma unroll
                for (int ni = 0; ni < 8; ni++)
                    mma16816(acc[mi][ni], al[mi], b[ni]);
        }
        __syncthreads();
        if (kc + 2 < nkc) load_stage((kc + 2) % STAGES, kc + 2);
    }

    // epilogue
    const int r0 = bm * 128 + wm * 32 + (lane >> 2);
    const int c0 = bn * 128 + wn * 64 + (lane & 3) * 2;
    #pragma unroll
    for (int mi = 0; mi < 2; mi++) {
        #pragma unroll
        for (int ni = 0; ni < 8; ni++) {
            int col = c0 + ni * 8;
            float bx = 0.f, by = 0.f;
            if (bias) { bx = bias[col]; by = bias[col + 1]; }
            float* p0 = C + (size_t)(r0 + mi * 16) * N + col;
            float* p1 = C + (size_t)(r0 + mi * 16 + 8) * N + col;
            *(float2*)p0 = make_float2(acc[mi][ni][0] + bx, acc[mi][ni][1] + by);
            *(float2*)p1 = make_float2(acc[mi][ni][2] + bx, acc[mi][ni][3] + by);
        }
    }
}

// ================= weight conversions (fp32 -> fp16) =================
__global__ void k_cvt(const float* __restrict__ x, __half* __restrict__ o, int n) {
    int i = blockIdx.x * blockDim.x + threadIdx.x;
    if (i < n) o[i] = __float2half_rn(x[i]);
}
// w[K][N] fp32 -> out[N][K] fp16
__global__ void k_cvt_t(const float* __restrict__ w, __half* __restrict__ o,
                        int K, int N) {
    int i = blockIdx.x * blockDim.x + threadIdx.x;
    if (i < K * N) {
        int k = i / N, n = i - k * N;
        o[(size_t)n * K + k] = __float2half_rn(w[i]);
    }
}
// batched per-layer transpose for ggnn_w [L][D][D]
__global__ void k_cvt_tb(const float* __restrict__ w, __half* __restrict__ o) {
    int i = blockIdx.x * blockDim.x + threadIdx.x;
    if (i < L_ * D_ * D_) {
        int l = i / (D_ * D_), r = i - l * (D_ * D_);
        int k = r / D_, n = r - k * D_;
        o[(size_t)l * D_ * D_ + (size_t)n * D_ + k] = __float2half_rn(w[i]);
    }
}

// ================= embed: type gather + contiguous 4-token mean -> fused =====
__global__ void k_embed(const int* __restrict__ types, const int* __restrict__ tok,
                        const int* __restrict__ lens, const float* __restrict__ table,
                        const float* __restrict__ emb, float* __restrict__ fused) {
    int bn = blockIdx.x;               // b*N + n
    int b = bn >> 9, n = bn & 511;
    int base = b * T_ + n * TPN_;
    int t0 = tok[base], t1 = tok[base + 1], t2 = tok[base + 2], t3 = tok[base + 3];
    float inv = 1.0f / (float)lens[bn];
    float* o = fused + (size_t)bn * F_;
    int d = threadIdx.x;               // 192
    if (d < TD_ / 4)
        ((float4*)o)[d] = ((const float4*)(table + (size_t)types[bn] * TD_))[d];
    float4 e0 = ((const float4*)(emb + (size_t)t0 * D_))[d];
    float4 e1 = ((const float4*)(emb + (size_t)t1 * D_))[d];
    float4 e2 = ((const float4*)(emb + (size_t)t2 * D_))[d];
    float4 e3 = ((const float4*)(emb + (size_t)t3 * D_))[d];
    float4 s;
    s.x = (e0.x + e1.x + e2.x + e3.x) * inv;
    s.y = (e0.y + e1.y + e2.y + e3.y) * inv;
    s.z = (e0.z + e1.z + e2.z + e3.z) * inv;
    s.w = (e0.w + e1.w + e2.w + e3.w) * inv;
    ((float4*)(o + TD_))[d] = s;
}

// ================= misc kernels =================
__global__ void k_zero(float4* __restrict__ p, int n4) {
    int i = blockIdx.x * blockDim.x + threadIdx.x;
    if (i < n4) p[i] = make_float4(0.f, 0.f, 0.f, 0.f);
}

__global__ void k_scatter(const int* __restrict__ esrc, const int* __restrict__ edst,
                          const float* __restrict__ ew, const float* __restrict__ msg,
                          float* __restrict__ agg) {
    int be = blockIdx.x;
    int b = be / E_;
    int s = esrc[be];
    int t = edst[be];
    float w = ew[be];
    const float4* mp = (const float4*)(msg + ((size_t)b * N_ + s) * D_);
    float* ap = agg + ((size_t)b * N_ + t) * D_;
    int d = threadIdx.x;               // 192
    float4 v = mp[d];
    asm volatile("red.global.add.v4.f32 [%0], {%1, %2, %3, %4};"
                 :: "l"(ap + d * 4), "f"(v.x * w), "f"(v.y * w),
                    "f"(v.z * w), "f"(v.w * w) : "memory");
}

__global__ void k_gru(const float* __restrict__ gi, const float* __restrict__ gh,
                      float* __restrict__ h) {
    int row = blockIdx.x;
    const float* gip = gi + (size_t)row * G_;
    const float* ghp = gh + (size_t)row * G_;
    float* hp = h + (size_t)row * D_;
    #pragma unroll
    for (int d = threadIdx.x; d < D_; d += 256) {
        float ir = gip[d], iz = gip[D_ + d], in = gip[2 * D_ + d];
        float hr = ghp[d], hz = ghp[D_ + d], hn = ghp[2 * D_ + d];
        float r = 1.0f / (1.0f + expf(-(ir + hr)));
        float z = 1.0f / (1.0f + expf(-(iz + hz)));
        float n = tanhf(in + r * hn);
        hp[d] = (1.0f - z) * n + z * hp[d];
    }
}

__global__ void k_out(const float* __restrict__ h, const int* __restrict__ keep,
                      float* __restrict__ out) {
    int bw = blockIdx.x;
    int b = bw >> 9;
    int wn = bw & 511;
    int kp = keep[b]; if (kp > 512) kp = 512;
    bool valid = wn < kp;
    const float4* hp = (const float4*)(h + (size_t)bw * D_);
    float4* op = (float4*)(out + (size_t)bw * D_);
    int d = threadIdx.x;
    float4 v = valid ? hp[d] : make_float4(0.f, 0.f, 0.f, 0.f);
    op[d] = v;
}

// ================= launch =================
extern "C" void kernel_launch(void* const* d_in, const int* in_sizes, int n_in,
                              void* d_out, int out_size) {
    const int*   node_types = (const int*)d_in[0];
    const int*   tok_ids    = (const int*)d_in[1];
    const int*   seg_ids    = (const int*)d_in[2]; (void)seg_ids;
    const int*   tok_lens   = (const int*)d_in[3];
    const int*   gnode_lens = (const int*)d_in[4];
    const int*   esrc       = (const int*)d_in[5];
    const int*   edst       = (const int*)d_in[6];
    const float* ew         = (const float*)d_in[7];
    const float* type_table = (const float*)d_in[8];
    const float* word_emb   = (const float*)d_in[9];
    const float* fusion_w   = (const float*)d_in[10];
    const float* fusion_b   = (const float*)d_in[11];
    const float* ggnn_w     = (const float*)d_in[12];
    const float* w_ih       = (const float*)d_in[13];
    const float* w_hh       = (const float*)d_in[14];
    const float* b_ih       = (const float*)d_in[15];
    const float* b_hh       = (const float*)d_in[16];
    float* out = (float*)d_out;

    cudaFuncSetAttribute(bmma, cudaFuncAttributeMaxDynamicSharedMemorySize, SMEM_SZ);

    float *fused, *h, *msg, *agg, *gi, *gh;
    cudaGetSymbolAddress((void**)&fused, g_fused);
    cudaGetSymbolAddress((void**)&h,     g_h);
    cudaGetSymbolAddress((void**)&msg,   g_msg);
    cudaGetSymbolAddress((void**)&agg,   g_agg);
    cudaGetSymbolAddress((void**)&gi,    g_gi);
    cudaGetSymbolAddress((void**)&gh,    g_gh);

    __half *fw, *gw, *ih, *hh;
    cudaGetSymbolAddress((void**)&fw, s_fw);
    cudaGetSymbolAddress((void**)&gw, s_gw);
    cudaGetSymbolAddress((void**)&ih, s_ih);
    cudaGetSymbolAddress((void**)&hh, s_hh);

    const int n4 = M_ * D_ / 4;

    // --- weight conversions ---
    k_cvt_t<<<(F_ * D_ + 255) / 256, 256>>>(fusion_w, fw, F_, D_);
    k_cvt_tb<<<(L_ * D_ * D_ + 255) / 256, 256>>>(ggnn_w, gw);
    k_cvt<<<(G_ * D_ + 255) / 256, 256>>>(w_ih, ih, G_ * D_);
    k_cvt<<<(G_ * D_ + 255) / 256, 256>>>(w_hh, hh, G_ * D_);

    // --- embeddings + mean + fusion input ---
    k_embed<<<M_, 192>>>(node_types, tok_ids, tok_lens, type_table, word_emb, fused);

    // h = fused @ fusion_w + fusion_b   [4096,896]x[896,768]
    bmma<<<dim3(D_ / 128, M_ / 128), 256, SMEM_SZ>>>(fused, fw, fusion_b, h, D_, F_);

    for (int l = 0; l < L_; ++l) {
        // msg = h @ ggnn_w[l]
        bmma<<<dim3(D_ / 128, M_ / 128), 256, SMEM_SZ>>>(
            h, gw + (size_t)l * D_ * D_, nullptr, msg, D_, D_);
        // agg = scatter_add(msg[src] * w -> dst)
        k_zero<<<(n4 + 255) / 256, 256>>>((float4*)agg, n4);
        k_scatter<<<B_ * E_, 192>>>(esrc, edst, ew, msg, agg);
        // gi = agg @ w_ih^T + b_ih ; gh = h @ w_hh^T + b_hh
        bmma<<<dim3(G_ / 128, M_ / 128), 256, SMEM_SZ>>>(agg, ih, b_ih, gi, G_, D_);
        bmma<<<dim3(G_ / 128, M_ / 128), 256, SMEM_SZ>>>(h, hh, b_hh, gh, G_, D_);
        // GRU update (in place on h)
        k_gru<<<M_, 256>>>(gi, gh, h);
    }

    k_out<<<M_, 192>>>(h, gnode_lens, out);
}

// round 6
// speedup vs baseline: 3.1806x; 1.1423x over previous
#include <cuda_runtime.h>
#include <cuda_fp16.h>
#include <cstdint>
#include <cstddef>

#define B_ 8
#define N_ 512
#define T_ 2048
#define E_ 4096
#define D_ 768
#define TD_ 128
#define L_ 4
#define F_ (TD_ + D_)   /* 896 */
#define G_ (3 * D_)     /* 2304 */
#define M_ (B_ * N_)    /* 4096 */
#define TPN_ (T_ / N_)  /* 4 tokens per node */

// ---------------- fp32 scratch ----------------
__device__ float g_fused[M_ * F_];
__device__ float g_h    [M_ * D_];
__device__ float g_msg  [M_ * D_];
__device__ float g_agg  [M_ * D_];
__device__ float g_gi   [M_ * G_];
__device__ float g_gh   [M_ * G_];

// ---------------- CSR scratch ----------------
__device__ int   g_cnt  [B_ * N_];
__device__ int   g_off  [B_ * (N_ + 1)];
__device__ int   g_pos  [B_ * N_];
__device__ int   g_src_s[B_ * E_];
__device__ float g_w_s  [B_ * E_];

// ---------------- fp16 weights (K-major) ----------------
__device__ __half s_fw[D_ * F_];        // fusion_w^T  [768][896]
__device__ __half s_gw[L_ * D_ * D_];   // ggnn_w[l]^T [768][768]
__device__ __half s_ih[G_ * D_];        // w_ih [2304][768]
__device__ __half s_hh[G_ * D_];

// ================= helpers =================
__device__ __forceinline__ uint32_t smem_u32(const void* p) {
    uint32_t a;
    asm("{ .reg .u64 t; cvta.to.shared.u64 t, %1; cvt.u32.u64 %0, t; }" : "=r"(a) : "l"(p));
    return a;
}
__device__ __forceinline__ void cp16(uint32_t saddr, const void* g) {
    asm volatile("cp.async.cg.shared.global [%0], [%1], 16;" :: "r"(saddr), "l"(g) : "memory");
}
#define CP_COMMIT() asm volatile("cp.async.commit_group;" ::: "memory")
#define CP_WAIT1()  asm volatile("cp.async.wait_group 1;" ::: "memory")

__device__ __forceinline__ void ldsm4(uint32_t& r0, uint32_t& r1, uint32_t& r2,
                                      uint32_t& r3, uint32_t a) {
    asm volatile("ldmatrix.sync.aligned.m8n8.x4.shared.b16 {%0,%1,%2,%3}, [%4];"
                 : "=r"(r0), "=r"(r1), "=r"(r2), "=r"(r3) : "r"(a));
}
__device__ __forceinline__ void mma16816(float* d, const uint32_t* a, const uint32_t* b) {
    asm volatile(
        "mma.sync.aligned.m16n8k16.row.col.f32.f16.f16.f32 "
        "{%0,%1,%2,%3}, {%4,%5,%6,%7}, {%8,%9}, {%0,%1,%2,%3};"
        : "+f"(d[0]), "+f"(d[1]), "+f"(d[2]), "+f"(d[3])
        : "r"(a[0]), "r"(a[1]), "r"(a[2]), "r"(a[3]), "r"(b[0]), "r"(b[1]));
}

// 8 fp32 -> 4x half2 hi + 4x half2 lo (packed)
__device__ __forceinline__ void cvt8(float4 f0, float4 f1, uint4& H, uint4& Lo) {
    __half2 h0 = __floats2half2_rn(f0.x, f0.y);
    __half2 h1 = __floats2half2_rn(f0.z, f0.w);
    __half2 h2 = __floats2half2_rn(f1.x, f1.y);
    __half2 h3 = __floats2half2_rn(f1.z, f1.w);
    __half2 l0 = __floats2half2_rn(f0.x - __half2float(h0.x), f0.y - __half2float(h0.y));
    __half2 l1 = __floats2half2_rn(f0.z - __half2float(h1.x), f0.w - __half2float(h1.y));
    __half2 l2 = __floats2half2_rn(f1.x - __half2float(h2.x), f1.y - __half2float(h2.y));
    __half2 l3 = __floats2half2_rn(f1.z - __half2float(h3.x), f1.w - __half2float(h3.y));
    H.x  = *(uint32_t*)&h0; H.y  = *(uint32_t*)&h1; H.z  = *(uint32_t*)&h2; H.w  = *(uint32_t*)&h3;
    Lo.x = *(uint32_t*)&l0; Lo.y = *(uint32_t*)&l1; Lo.z = *(uint32_t*)&l2; Lo.w = *(uint32_t*)&l3;
}

// smem tile: 128 rows x 32 halves (64B) + 16B pad -> 80B row stride
#define ROWB    80
#define TILEB   (128 * ROWB)          /* 10240 */
#define STAGEB  (3 * TILEB)           /* Ahi, Alo, B = 30720 */
#define STAGES  3
#define SMEM_SZ (STAGES * STAGEB)     /* 92160 */

// ================= mma.sync 2-term fp16 GEMM, fp32 A split on the fly ========
// C[M,N] = A[M,K](fp32) @ Bh[N,K]^T via (Ahi + Alo) * Bh, fp32 accum, + bias.
// grid=(N/128, M/128), block=256, dyn smem = SMEM_SZ. K%32==0, N%128==0.
// Prefetch structure: at top of iteration kc, issue cp.async(B) and LDG(A) for
// stage kc+2 so global latency hides behind compute(kc).
__global__ void __launch_bounds__(256) bmma(
    const float* __restrict__ A, const __half* __restrict__ Bh,
    const float* __restrict__ bias, float* __restrict__ C, int N, int K)
{
    extern __shared__ char smem[];
    const uint32_t sbase = smem_u32(smem);
    const int tid = threadIdx.x;
    const int wid = tid >> 5, lane = tid & 31;
    const int wm = wid & 3, wn = wid >> 2;           // 4x2 warp grid
    const int bn = blockIdx.x, bm = blockIdx.y;

    const int nkc = K >> 5;

    // B loader lanes (cp.async, 16B each)
    const int lrow0 = tid >> 2;
    const int lrow1 = 64 + (tid >> 2);
    const int lseg  = tid & 3;
    // A loader lanes (fp32 LDG + convert + STS)
    const int ar = tid >> 1;          // row 0..127
    const int asg = tid & 1;          // 16-float half

    auto load_stage = [&](int stage, int kc) {   // synchronous (prologue only)
        uint32_t sb = sbase + stage * STAGEB;
        int kof = kc * 32;
        cp16(sb + 2 * TILEB + lrow0 * ROWB + lseg * 16,
             Bh + (size_t)(bn * 128 + lrow0) * K + kof + lseg * 8);
        cp16(sb + 2 * TILEB + lrow1 * ROWB + lseg * 16,
             Bh + (size_t)(bn * 128 + lrow1) * K + kof + lseg * 8);
        CP_COMMIT();
        const float4* Ap = (const float4*)(A + (size_t)(bm * 128 + ar) * K + kof + asg * 16);
        float4 f0 = Ap[0], f1 = Ap[1], f2 = Ap[2], f3 = Ap[3];
        uint4 H0, L0, H1, L1;
        cvt8(f0, f1, H0, L0);
        cvt8(f2, f3, H1, L1);
        char* arow = smem + stage * STAGEB + ar * ROWB + asg * 32;
        *(uint4*)(arow)              = H0;
        *(uint4*)(arow + 16)         = H1;
        *(uint4*)(arow + TILEB)      = L0;
        *(uint4*)(arow + TILEB + 16) = L1;
    };

    float acc[2][8][4];
    #pragma unroll
    for (int i = 0; i < 2; i++)
        #pragma unroll
        for (int j = 0; j < 8; j++)
            #pragma unroll
            for (int q = 0; q < 4; q++) acc[i][j][q] = 0.f;

    load_stage(0, 0);
    load_stage(1, 1);

    const int a_row  = wm * 32 + (lane & 15);
    const int a_colb = (lane >> 4) * 16;
    const int b_row  = wn * 64 + (lane & 7) + ((lane >> 4) << 3);
    const int b_colb = ((lane >> 3) & 1) * 16;

    for (int kc = 0; kc < nkc; kc++) {
        const bool pf = (kc + 2 < nkc);
        float4 f0, f1, f2, f3;
        const int st2 = (kc + 2) % STAGES;
        if (pf) {
            // issue next-next stage loads NOW; data lands while we compute
            uint32_t sb = sbase + st2 * STAGEB;
            int kof = (kc + 2) * 32;
            cp16(sb + 2 * TILEB + lrow0 * ROWB + lseg * 16,
                 Bh + (size_t)(bn * 128 + lrow0) * K + kof + lseg * 8);
            cp16(sb + 2 * TILEB + lrow1 * ROWB + lseg * 16,
                 Bh + (size_t)(bn * 128 + lrow1) * K + kof + lseg * 8);
            CP_COMMIT();
            const float4* Ap = (const float4*)(A + (size_t)(bm * 128 + ar) * K + kof + asg * 16);
            f0 = Ap[0]; f1 = Ap[1]; f2 = Ap[2]; f3 = Ap[3];
        }

        CP_WAIT1();
        __syncthreads();
        uint32_t st = sbase + (kc % STAGES) * STAGEB;
        uint32_t sah = st, sal = st + TILEB, sbh = st + 2 * TILEB;

        #pragma unroll
        for (int ks = 0; ks < 2; ks++) {
            uint32_t ah[2][4], al[2][4], b[8][2];
            #pragma unroll
            for (int mi = 0; mi < 2; mi++)
                ldsm4(ah[mi][0], ah[mi][1], ah[mi][2], ah[mi][3],
                      sah + (a_row + mi * 16) * ROWB + ks * 32 + a_colb);
            #pragma unroll
            for (int np = 0; np < 4; np++) {
                uint32_t r0, r1, r2, r3;
                ldsm4(r0, r1, r2, r3, sbh + (b_row + np * 16) * ROWB + ks * 32 + b_colb);
                b[np * 2 + 0][0] = r0; b[np * 2 + 0][1] = r1;
                b[np * 2 + 1][0] = r2; b[np * 2 + 1][1] = r3;
            }
            #pragma unroll
            for (int mi = 0; mi < 2; mi++)
                #pragma unroll
                for (int ni = 0; ni < 8; ni++)
                    mma16816(acc[mi][ni], ah[mi], b[ni]);
            #pragma unroll
            for (int mi = 0; mi < 2; mi++)
                ldsm4(al[mi][0], al[mi][1], al[mi][2], al[mi][3],
                      sal + (a_row + mi * 16) * ROWB + ks * 32 + a_colb);
            #pragma unroll
            for (int mi = 0; mi < 2; mi++)
                #pragma unroll
                for (int ni = 0; ni < 8; ni++)
                    mma16816(acc[mi][ni], al[mi], b[ni]);
        }

        if (pf) {
            uint4 H0, L0, H1, L1;
            cvt8(f0, f1, H0, L0);
            cvt8(f2, f3, H1, L1);
            char* arow = smem + st2 * STAGEB + ar * ROWB + asg * 32;
            *(uint4*)(arow)              = H0;
            *(uint4*)(arow + 16)         = H1;
            *(uint4*)(arow + TILEB)      = L0;
            *(uint4*)(arow + TILEB + 16) = L1;
        }
        __syncthreads();   // compute(kc) done before next iter's cp.async reuses stage kc%3
    }

    // epilogue
    const int r0 = bm * 128 + wm * 32 + (lane >> 2);
    const int c0 = bn * 128 + wn * 64 + (lane & 3) * 2;
    #pragma unroll
    for (int mi = 0; mi < 2; mi++) {
        #pragma unroll
        for (int ni = 0; ni < 8; ni++) {
            int col = c0 + ni * 8;
            float bx = 0.f, by = 0.f;
            if (bias) { bx = bias[col]; by = bias[col + 1]; }
            float* p0 = C + (size_t)(r0 + mi * 16) * N + col;
            float* p1 = C + (size_t)(r0 + mi * 16 + 8) * N + col;
            *(float2*)p0 = make_float2(acc[mi][ni][0] + bx, acc[mi][ni][1] + by);
            *(float2*)p1 = make_float2(acc[mi][ni][2] + bx, acc[mi][ni][3] + by);
        }
    }
}

// ================= weight conversions (fp32 -> fp16) =================
__global__ void k_cvt(const float* __restrict__ x, __half* __restrict__ o, int n) {
    int i = blockIdx.x * blockDim.x + threadIdx.x;
    if (i < n) o[i] = __float2half_rn(x[i]);
}
__global__ void k_cvt_t(const float* __restrict__ w, __half* __restrict__ o,
                        int K, int N) {
    int i = blockIdx.x * blockDim.x + threadIdx.x;
    if (i < K * N) {
        int k = i / N, n = i - k * N;
        o[(size_t)n * K + k] = __float2half_rn(w[i]);
    }
}
__global__ void k_cvt_tb(const float* __restrict__ w, __half* __restrict__ o) {
    int i = blockIdx.x * blockDim.x + threadIdx.x;
    if (i < L_ * D_ * D_) {
        int l = i / (D_ * D_), r = i - l * (D_ * D_);
        int k = r / D_, n = r - k * D_;
        o[(size_t)l * D_ * D_ + (size_t)n * D_ + k] = __float2half_rn(w[i]);
    }
}

// ================= CSR build (by dst, per batch) =================
__global__ void k_zero_i(int* __restrict__ p, int n) {
    int i = blockIdx.x * blockDim.x + threadIdx.x;
    if (i < n) p[i] = 0;
}
__global__ void k_count(const int* __restrict__ edst, int* __restrict__ cnt) {
    int be = blockIdx.x * blockDim.x + threadIdx.x;
    if (be < B_ * E_) {
        int b = be / E_;
        atomicAdd(&cnt[b * N_ + edst[be]], 1);
    }
}
__global__ void k_prefix(const int* __restrict__ cnt, int* __restrict__ off,
                         int* __restrict__ pos) {
    __shared__ int s[N_];
    int b = blockIdx.x, n = threadIdx.x;    // 512 threads
    int v = cnt[b * N_ + n];
    s[n] = v;
    __syncthreads();
    #pragma unroll
    for (int d = 1; d < N_; d <<= 1) {
        int t = (n >= d) ? s[n - d] : 0;
        __syncthreads();
        s[n] += t;
        __syncthreads();
    }
    off[b * (N_ + 1) + n + 1] = s[n];
    if (n == 0) off[b * (N_ + 1)] = 0;
    pos[b * N_ + n] = s[n] - v;             // exclusive
}
__global__ void k_fill(const int* __restrict__ esrc, const int* __restrict__ edst,
                       const float* __restrict__ ew, int* __restrict__ pos,
                       int* __restrict__ src_s, float* __restrict__ w_s) {
    int be = blockIdx.x * blockDim.x + threadIdx.x;
    if (be < B_ * E_) {
        int b = be / E_;
        int p = atomicAdd(&pos[b * N_ + edst[be]], 1);
        src_s[b * E_ + p] = esrc[be];
        w_s[b * E_ + p] = ew[be];
    }
}
// agg[b,n,:] = sum over incoming edges (msg[b,src] * w). No atomics, no zero pass.
__global__ void k_gather(const int* __restrict__ off, const int* __restrict__ src_s,
                         const float* __restrict__ w_s, const float* __restrict__ msg,
                         float* __restrict__ agg) {
    int bn = blockIdx.x;
    int b = bn >> 9, n = bn & 511;
    int o0 = off[b * (N_ + 1) + n], o1 = off[b * (N_ + 1) + n + 1];
    int d = threadIdx.x;               // 192
    float4 acc = make_float4(0.f, 0.f, 0.f, 0.f);
    const float* mb = msg + (size_t)b * N_ * D_;
    for (int e = o0; e < o1; e++) {
        int s = src_s[b * E_ + e];
        float w = w_s[b * E_ + e];
        float4 v = ((const float4*)(mb + (size_t)s * D_))[d];
        acc.x += v.x * w; acc.y += v.y * w; acc.z += v.z * w; acc.w += v.w * w;
    }
    ((float4*)(agg + (size_t)bn * D_))[d] = acc;
}

// ================= embed: type gather + contiguous 4-token mean -> fused =====
__global__ void k_embed(const int* __restrict__ types, const int* __restrict__ tok,
                        const int* __restrict__ lens, const float* __restrict__ table,
                        const float* __restrict__ emb, float* __restrict__ fused) {
    int bn = blockIdx.x;
    int b = bn >> 9, n = bn & 511;
    int base = b * T_ + n * TPN_;
    int t0 = tok[base], t1 = tok[base + 1], t2 = tok[base + 2], t3 = tok[base + 3];
    float inv = 1.0f / (float)lens[bn];
    float* o = fused + (size_t)bn * F_;
    int d = threadIdx.x;               // 192
    if (d < TD_ / 4)
        ((float4*)o)[d] = ((const float4*)(table + (size_t)types[bn] * TD_))[d];
    float4 e0 = ((const float4*)(emb + (size_t)t0 * D_))[d];
    float4 e1 = ((const float4*)(emb + (size_t)t1 * D_))[d];
    float4 e2 = ((const float4*)(emb + (size_t)t2 * D_))[d];
    float4 e3 = ((const float4*)(emb + (size_t)t3 * D_))[d];
    float4 s;
    s.x = (e0.x + e1.x + e2.x + e3.x) * inv;
    s.y = (e0.y + e1.y + e2.y + e3.y) * inv;
    s.z = (e0.z + e1.z + e2.z + e3.z) * inv;
    s.w = (e0.w + e1.w + e2.w + e3.w) * inv;
    ((float4*)(o + TD_))[d] = s;
}

// ================= GRU + output =================
__global__ void k_gru(const float* __restrict__ gi, const float* __restrict__ gh,
                      float* __restrict__ h) {
    int row = blockIdx.x;
    const float* gip = gi + (size_t)row * G_;
    const float* ghp = gh + (size_t)row * G_;
    float* hp = h + (size_t)row * D_;
    #pragma unroll
    for (int d = threadIdx.x; d < D_; d += 256) {
        float ir = gip[d], iz = gip[D_ + d], in = gip[2 * D_ + d];
        float hr = ghp[d], hz = ghp[D_ + d], hn = ghp[2 * D_ + d];
        float r = 1.0f / (1.0f + expf(-(ir + hr)));
        float z = 1.0f / (1.0f + expf(-(iz + hz)));
        float n = tanhf(in + r * hn);
        hp[d] = (1.0f - z) * n + z * hp[d];
    }
}

__global__ void k_out(const float* __restrict__ h, const int* __restrict__ keep,
                      float* __restrict__ out) {
    int bw = blockIdx.x;
    int b = bw >> 9;
    int wn = bw & 511;
    int kp = keep[b]; if (kp > 512) kp = 512;
    bool valid = wn < kp;
    const float4* hp = (const float4*)(h + (size_t)bw * D_);
    float4* op = (float4*)(out + (size_t)bw * D_);
    int d = threadIdx.x;
    float4 v = valid ? hp[d] : make_float4(0.f, 0.f, 0.f, 0.f);
    op[d] = v;
}

// ================= launch =================
extern "C" void kernel_launch(void* const* d_in, const int* in_sizes, int n_in,
                              void* d_out, int out_size) {
    const int*   node_types = (const int*)d_in[0];
    const int*   tok_ids    = (const int*)d_in[1];
    const int*   seg_ids    = (const int*)d_in[2]; (void)seg_ids;
    const int*   tok_lens   = (const int*)d_in[3];
    const int*   gnode_lens = (const int*)d_in[4];
    const int*   esrc       = (const int*)d_in[5];
    const int*   edst       = (const int*)d_in[6];
    const float* ew         = (const float*)d_in[7];
    const float* type_table = (const float*)d_in[8];
    const float* word_emb   = (const float*)d_in[9];
    const float* fusion_w   = (const float*)d_in[10];
    const float* fusion_b   = (const float*)d_in[11];
    const float* ggnn_w     = (const float*)d_in[12];
    const float* w_ih       = (const float*)d_in[13];
    const float* w_hh       = (const float*)d_in[14];
    const float* b_ih       = (const float*)d_in[15];
    const float* b_hh       = (const float*)d_in[16];
    float* out = (float*)d_out;

    cudaFuncSetAttribute(bmma, cudaFuncAttributeMaxDynamicSharedMemorySize, SMEM_SZ);

    float *fused, *h, *msg, *agg, *gi, *gh;
    cudaGetSymbolAddress((void**)&fused, g_fused);
    cudaGetSymbolAddress((void**)&h,     g_h);
    cudaGetSymbolAddress((void**)&msg,   g_msg);
    cudaGetSymbolAddress((void**)&agg,   g_agg);
    cudaGetSymbolAddress((void**)&gi,    g_gi);
    cudaGetSymbolAddress((void**)&gh,    g_gh);

    __half *fw, *gw, *ih, *hh;
    cudaGetSymbolAddress((void**)&fw, s_fw);
    cudaGetSymbolAddress((void**)&gw, s_gw);
    cudaGetSymbolAddress((void**)&ih, s_ih);
    cudaGetSymbolAddress((void**)&hh, s_hh);

    int *cnt, *off, *pos, *src_s; float *w_s;
    cudaGetSymbolAddress((void**)&cnt,   g_cnt);
    cudaGetSymbolAddress((void**)&off,   g_off);
    cudaGetSymbolAddress((void**)&pos,   g_pos);
    cudaGetSymbolAddress((void**)&src_s, g_src_s);
    cudaGetSymbolAddress((void**)&w_s,   g_w_s);

    // --- weight conversions ---
    k_cvt_t<<<(F_ * D_ + 255) / 256, 256>>>(fusion_w, fw, F_, D_);
    k_cvt_tb<<<(L_ * D_ * D_ + 255) / 256, 256>>>(ggnn_w, gw);
    k_cvt<<<(G_ * D_ + 255) / 256, 256>>>(w_ih, ih, G_ * D_);
    k_cvt<<<(G_ * D_ + 255) / 256, 256>>>(w_hh, hh, G_ * D_);

    // --- CSR build (by dst) ---
    k_zero_i<<<(B_ * N_ + 255) / 256, 256>>>(cnt, B_ * N_);
    k_count<<<(B_ * E_ + 255) / 256, 256>>>(edst, cnt);
    k_prefix<<<B_, N_>>>(cnt, off, pos);
    k_fill<<<(B_ * E_ + 255) / 256, 256>>>(esrc, edst, ew, pos, src_s, w_s);

    // --- embeddings + mean + fusion input ---
    k_embed<<<M_, 192>>>(node_types, tok_ids, tok_lens, type_table, word_emb, fused);

    // h = fused @ fusion_w + fusion_b   [4096,896]x[896,768]
    bmma<<<dim3(D_ / 128, M_ / 128), 256, SMEM_SZ>>>(fused, fw, fusion_b, h, D_, F_);

    for (int l = 0; l < L_; ++l) {
        // msg = h @ ggnn_w[l]
        bmma<<<dim3(D_ / 128, M_ / 128), 256, SMEM_SZ>>>(
            h, gw + (size_t)l * D_ * D_, nullptr, msg, D_, D_);
        // agg = CSR gather of msg[src] * w into dst rows
        k_gather<<<M_, 192>>>(off, src_s, w_s, msg, agg);
        // gi = agg @ w_ih^T + b_ih ; gh = h @ w_hh^T + b_hh
        bmma<<<dim3(G_ / 128, M_ / 128), 256, SMEM_SZ>>>(agg, ih, b_ih, gi, G_, D_);
        bmma<<<dim3(G_ / 128, M_ / 128), 256, SMEM_SZ>>>(h, hh, b_hh, gh, G_, D_);
        // GRU update (in place on h)
        k_gru<<<M_, 256>>>(gi, gh, h);
    }

    k_out<<<M_, 192>>>(h, gnode_lens, out);
}

// round 7
// speedup vs baseline: 3.3258x; 1.0457x over previous
#include <cuda_runtime.h>
#include <cuda_fp16.h>
#include <cstdint>
#include <cstddef>

#define B_ 8
#define N_ 512
#define T_ 2048
#define E_ 4096
#define D_ 768
#define TD_ 128
#define L_ 4
#define F_ (TD_ + D_)   /* 896 */
#define G_ (3 * D_)     /* 2304 */
#define M_ (B_ * N_)    /* 4096 */
#define TPN_ (T_ / N_)  /* 4 tokens per node */

// ---------------- fp32 scratch ----------------
__device__ float g_fused[M_ * F_];
__device__ float g_h    [M_ * D_];
__device__ float g_msg  [M_ * D_];
__device__ float g_agg  [M_ * D_];
__device__ float g_gi   [M_ * G_];
__device__ float g_gh   [M_ * G_];

// ---------------- CSR scratch ----------------
__device__ int   g_cnt  [B_ * N_];
__device__ int   g_off  [B_ * (N_ + 1)];
__device__ int   g_pos  [B_ * N_];
__device__ int   g_src_s[B_ * E_];
__device__ float g_w_s  [B_ * E_];

// ---------------- fp16 weights (K-major) ----------------
__device__ __half s_fw[D_ * F_];        // fusion_w^T  [768][896]
__device__ __half s_gw[L_ * D_ * D_];   // ggnn_w[l]^T [768][768]
__device__ __half s_ih[G_ * D_];        // w_ih [2304][768]
__device__ __half s_hh[G_ * D_];

// ================= helpers =================
__device__ __forceinline__ uint32_t smem_u32(const void* p) {
    uint32_t a;
    asm("{ .reg .u64 t; cvta.to.shared.u64 t, %1; cvt.u32.u64 %0, t; }" : "=r"(a) : "l"(p));
    return a;
}
__device__ __forceinline__ void cp16(uint32_t saddr, const void* g) {
    asm volatile("cp.async.cg.shared.global [%0], [%1], 16;" :: "r"(saddr), "l"(g) : "memory");
}
#define CP_COMMIT() asm volatile("cp.async.commit_group;" ::: "memory")
#define CP_WAIT1()  asm volatile("cp.async.wait_group 1;" ::: "memory")

__device__ __forceinline__ void ldsm4(uint32_t& r0, uint32_t& r1, uint32_t& r2,
                                      uint32_t& r3, uint32_t a) {
    asm volatile("ldmatrix.sync.aligned.m8n8.x4.shared.b16 {%0,%1,%2,%3}, [%4];"
                 : "=r"(r0), "=r"(r1), "=r"(r2), "=r"(r3) : "r"(a));
}
__device__ __forceinline__ void mma16816(float* d, const uint32_t* a, const uint32_t* b) {
    asm volatile(
        "mma.sync.aligned.m16n8k16.row.col.f32.f16.f16.f32 "
        "{%0,%1,%2,%3}, {%4,%5,%6,%7}, {%8,%9}, {%0,%1,%2,%3};"
        : "+f"(d[0]), "+f"(d[1]), "+f"(d[2]), "+f"(d[3])
        : "r"(a[0]), "r"(a[1]), "r"(a[2]), "r"(a[3]), "r"(b[0]), "r"(b[1]));
}

// 8 fp32 -> 4x half2 hi + 4x half2 lo (packed)
__device__ __forceinline__ void cvt8(float4 f0, float4 f1, uint4& H, uint4& Lo) {
    __half2 h0 = __floats2half2_rn(f0.x, f0.y);
    __half2 h1 = __floats2half2_rn(f0.z, f0.w);
    __half2 h2 = __floats2half2_rn(f1.x, f1.y);
    __half2 h3 = __floats2half2_rn(f1.z, f1.w);
    __half2 l0 = __floats2half2_rn(f0.x - __half2float(h0.x), f0.y - __half2float(h0.y));
    __half2 l1 = __floats2half2_rn(f0.z - __half2float(h1.x), f0.w - __half2float(h1.y));
    __half2 l2 = __floats2half2_rn(f1.x - __half2float(h2.x), f1.y - __half2float(h2.y));
    __half2 l3 = __floats2half2_rn(f1.z - __half2float(h3.x), f1.w - __half2float(h3.y));
    H.x  = *(uint32_t*)&h0; H.y  = *(uint32_t*)&h1; H.z  = *(uint32_t*)&h2; H.w  = *(uint32_t*)&h3;
    Lo.x = *(uint32_t*)&l0; Lo.y = *(uint32_t*)&l1; Lo.z = *(uint32_t*)&l2; Lo.w = *(uint32_t*)&l3;
}

// smem tile: 128 rows x 32 halves (64B) + 16B pad -> 80B row stride
#define ROWB    80
#define TILEB   (128 * ROWB)          /* 10240 */
#define STAGEB  (3 * TILEB)           /* Ahi, Alo, B = 30720 */
#define STAGES  3
#define SMEM_SZ (STAGES * STAGEB)     /* 92160 */

// ================= mma.sync 2-term fp16 GEMM, fp32 A split on the fly ========
__global__ void __launch_bounds__(256) bmma(
    const float* __restrict__ A, const __half* __restrict__ Bh,
    const float* __restrict__ bias, float* __restrict__ C, int N, int K)
{
    extern __shared__ char smem[];
    const uint32_t sbase = smem_u32(smem);
    const int tid = threadIdx.x;
    const int wid = tid >> 5, lane = tid & 31;
    const int wm = wid & 3, wn = wid >> 2;           // 4x2 warp grid
    const int bn = blockIdx.x, bm = blockIdx.y;

    const int nkc = K >> 5;

    const int lrow0 = tid >> 2;
    const int lrow1 = 64 + (tid >> 2);
    const int lseg  = tid & 3;
    const int ar = tid >> 1;
    const int asg = tid & 1;

    auto load_stage = [&](int stage, int kc) {   // synchronous (prologue only)
        uint32_t sb = sbase + stage * STAGEB;
        int kof = kc * 32;
        cp16(sb + 2 * TILEB + lrow0 * ROWB + lseg * 16,
             Bh + (size_t)(bn * 128 + lrow0) * K + kof + lseg * 8);
        cp16(sb + 2 * TILEB + lrow1 * ROWB + lseg * 16,
             Bh + (size_t)(bn * 128 + lrow1) * K + kof + lseg * 8);
        CP_COMMIT();
        const float4* Ap = (const float4*)(A + (size_t)(bm * 128 + ar) * K + kof + asg * 16);
        float4 f0 = Ap[0], f1 = Ap[1], f2 = Ap[2], f3 = Ap[3];
        uint4 H0, L0, H1, L1;
        cvt8(f0, f1, H0, L0);
        cvt8(f2, f3, H1, L1);
        char* arow = smem + stage * STAGEB + ar * ROWB + asg * 32;
        *(uint4*)(arow)              = H0;
        *(uint4*)(arow + 16)         = H1;
        *(uint4*)(arow + TILEB)      = L0;
        *(uint4*)(arow + TILEB + 16) = L1;
    };

    float acc[2][8][4];
    #pragma unroll
    for (int i = 0; i < 2; i++)
        #pragma unroll
        for (int j = 0; j < 8; j++)
            #pragma unroll
            for (int q = 0; q < 4; q++) acc[i][j][q] = 0.f;

    load_stage(0, 0);
    load_stage(1, 1);

    const int a_row  = wm * 32 + (lane & 15);
    const int a_colb = (lane >> 4) * 16;
    const int b_row  = wn * 64 + (lane & 7) + ((lane >> 4) << 3);
    const int b_colb = ((lane >> 3) & 1) * 16;

    for (int kc = 0; kc < nkc; kc++) {
        const bool pf = (kc + 2 < nkc);
        float4 f0, f1, f2, f3;
        const int st2 = (kc + 2) % STAGES;
        if (pf) {
            uint32_t sb = sbase + st2 * STAGEB;
            int kof = (kc + 2) * 32;
            cp16(sb + 2 * TILEB + lrow0 * ROWB + lseg * 16,
                 Bh + (size_t)(bn * 128 + lrow0) * K + kof + lseg * 8);
            cp16(sb + 2 * TILEB + lrow1 * ROWB + lseg * 16,
                 Bh + (size_t)(bn * 128 + lrow1) * K + kof + lseg * 8);
            CP_COMMIT();
            const float4* Ap = (const float4*)(A + (size_t)(bm * 128 + ar) * K + kof + asg * 16);
            f0 = Ap[0]; f1 = Ap[1]; f2 = Ap[2]; f3 = Ap[3];
        }

        CP_WAIT1();
        __syncthreads();
        uint32_t st = sbase + (kc % STAGES) * STAGEB;
        uint32_t sah = st, sal = st + TILEB, sbh = st + 2 * TILEB;

        #pragma unroll
        for (int ks = 0; ks < 2; ks++) {
            uint32_t ah[2][4], al[2][4], b[8][2];
            #pragma unroll
            for (int mi = 0; mi < 2; mi++)
                ldsm4(ah[mi][0], ah[mi][1], ah[mi][2], ah[mi][3],
                      sah + (a_row + mi * 16) * ROWB + ks * 32 + a_colb);
            #pragma unroll
            for (int np = 0; np < 4; np++) {
                uint32_t r0, r1, r2, r3;
                ldsm4(r0, r1, r2, r3, sbh + (b_row + np * 16) * ROWB + ks * 32 + b_colb);
                b[np * 2 + 0][0] = r0; b[np * 2 + 0][1] = r1;
                b[np * 2 + 1][0] = r2; b[np * 2 + 1][1] = r3;
            }
            #pragma unroll
            for (int mi = 0; mi < 2; mi++)
                #pragma unroll
                for (int ni = 0; ni < 8; ni++)
                    mma16816(acc[mi][ni], ah[mi], b[ni]);
            #pragma unroll
            for (int mi = 0; mi < 2; mi++)
                ldsm4(al[mi][0], al[mi][1], al[mi][2], al[mi][3],
                      sal + (a_row + mi * 16) * ROWB + ks * 32 + a_colb);
            #pragma unroll
            for (int mi = 0; mi < 2; mi++)
                #pragma unroll
                for (int ni = 0; ni < 8; ni++)
                    mma16816(acc[mi][ni], al[mi], b[ni]);
        }

        if (pf) {
            uint4 H0, L0, H1, L1;
            cvt8(f0, f1, H0, L0);
            cvt8(f2, f3, H1, L1);
            char* arow = smem + st2 * STAGEB + ar * ROWB + asg * 32;
            *(uint4*)(arow)              = H0;
            *(uint4*)(arow + 16)         = H1;
            *(uint4*)(arow + TILEB)      = L0;
            *(uint4*)(arow + TILEB + 16) = L1;
        }
        __syncthreads();
    }

    // epilogue
    const int r0 = bm * 128 + wm * 32 + (lane >> 2);
    const int c0 = bn * 128 + wn * 64 + (lane & 3) * 2;
    #pragma unroll
    for (int mi = 0; mi < 2; mi++) {
        #pragma unroll
        for (int ni = 0; ni < 8; ni++) {
            int col = c0 + ni * 8;
            float bx = 0.f, by = 0.f;
            if (bias) { bx = bias[col]; by = bias[col + 1]; }
            float* p0 = C + (size_t)(r0 + mi * 16) * N + col;
            float* p1 = C + (size_t)(r0 + mi * 16 + 8) * N + col;
            *(float2*)p0 = make_float2(acc[mi][ni][0] + bx, acc[mi][ni][1] + by);
            *(float2*)p1 = make_float2(acc[mi][ni][2] + bx, acc[mi][ni][3] + by);
        }
    }
}

// ================= weight conversions (fp32 -> fp16) =================
__global__ void k_cvt(const float* __restrict__ x, __half* __restrict__ o, int n) {
    int i = blockIdx.x * blockDim.x + threadIdx.x;
    if (i < n) o[i] = __float2half_rn(x[i]);
}
__global__ void k_cvt_t(const float* __restrict__ w, __half* __restrict__ o,
                        int K, int N) {
    int i = blockIdx.x * blockDim.x + threadIdx.x;
    if (i < K * N) {
        int k = i / N, n = i - k * N;
        o[(size_t)n * K + k] = __float2half_rn(w[i]);
    }
}
__global__ void k_cvt_tb(const float* __restrict__ w, __half* __restrict__ o) {
    int i = blockIdx.x * blockDim.x + threadIdx.x;
    if (i < L_ * D_ * D_) {
        int l = i / (D_ * D_), r = i - l * (D_ * D_);
        int k = r / D_, n = r - k * D_;
        o[(size_t)l * D_ * D_ + (size_t)n * D_ + k] = __float2half_rn(w[i]);
    }
}

// ================= CSR build (by dst, per batch) =================
__global__ void k_zero_i(int* __restrict__ p, int n) {
    int i = blockIdx.x * blockDim.x + threadIdx.x;
    if (i < n) p[i] = 0;
}
__global__ void k_count(const int* __restrict__ edst, int* __restrict__ cnt) {
    int be = blockIdx.x * blockDim.x + threadIdx.x;
    if (be < B_ * E_) {
        int b = be / E_;
        atomicAdd(&cnt[b * N_ + edst[be]], 1);
    }
}
__global__ void k_prefix(const int* __restrict__ cnt, int* __restrict__ off,
                         int* __restrict__ pos) {
    __shared__ int s[N_];
    int b = blockIdx.x, n = threadIdx.x;
    int v = cnt[b * N_ + n];
    s[n] = v;
    __syncthreads();
    #pragma unroll
    for (int d = 1; d < N_; d <<= 1) {
        int t = (n >= d) ? s[n - d] : 0;
        __syncthreads();
        s[n] += t;
        __syncthreads();
    }
    off[b * (N_ + 1) + n + 1] = s[n];
    if (n == 0) off[b * (N_ + 1)] = 0;
    pos[b * N_ + n] = s[n] - v;
}
__global__ void k_fill(const int* __restrict__ esrc, const int* __restrict__ edst,
                       const float* __restrict__ ew, int* __restrict__ pos,
                       int* __restrict__ src_s, float* __restrict__ w_s) {
    int be = blockIdx.x * blockDim.x + threadIdx.x;
    if (be < B_ * E_) {
        int b = be / E_;
        int p = atomicAdd(&pos[b * N_ + edst[be]], 1);
        src_s[b * E_ + p] = esrc[be];
        w_s[b * E_ + p] = ew[be];
    }
}
__global__ void k_gather(const int* __restrict__ off, const int* __restrict__ src_s,
                         const float* __restrict__ w_s, const float* __restrict__ msg,
                         float* __restrict__ agg) {
    int bn = blockIdx.x;
    int b = bn >> 9, n = bn & 511;
    int o0 = off[b * (N_ + 1) + n], o1 = off[b * (N_ + 1) + n + 1];
    int d = threadIdx.x;
    float4 acc = make_float4(0.f, 0.f, 0.f, 0.f);
    const float* mb = msg + (size_t)b * N_ * D_;
    for (int e = o0; e < o1; e++) {
        int s = src_s[b * E_ + e];
        float w = w_s[b * E_ + e];
        float4 v = ((const float4*)(mb + (size_t)s * D_))[d];
        acc.x += v.x * w; acc.y += v.y * w; acc.z += v.z * w; acc.w += v.w * w;
    }
    ((float4*)(agg + (size_t)bn * D_))[d] = acc;
}

// ================= embed =================
__global__ void k_embed(const int* __restrict__ types, const int* __restrict__ tok,
                        const int* __restrict__ lens, const float* __restrict__ table,
                        const float* __restrict__ emb, float* __restrict__ fused) {
    int bn = blockIdx.x;
    int b = bn >> 9, n = bn & 511;
    int base = b * T_ + n * TPN_;
    int t0 = tok[base], t1 = tok[base + 1], t2 = tok[base + 2], t3 = tok[base + 3];
    float inv = 1.0f / (float)lens[bn];
    float* o = fused + (size_t)bn * F_;
    int d = threadIdx.x;
    if (d < TD_ / 4)
        ((float4*)o)[d] = ((const float4*)(table + (size_t)types[bn] * TD_))[d];
    float4 e0 = ((const float4*)(emb + (size_t)t0 * D_))[d];
    float4 e1 = ((const float4*)(emb + (size_t)t1 * D_))[d];
    float4 e2 = ((const float4*)(emb + (size_t)t2 * D_))[d];
    float4 e3 = ((const float4*)(emb + (size_t)t3 * D_))[d];
    float4 s;
    s.x = (e0.x + e1.x + e2.x + e3.x) * inv;
    s.y = (e0.y + e1.y + e2.y + e3.y) * inv;
    s.z = (e0.z + e1.z + e2.z + e3.z) * inv;
    s.w = (e0.w + e1.w + e2.w + e3.w) * inv;
    ((float4*)(o + TD_))[d] = s;
}

// ================= GRU + output =================
__global__ void k_gru(const float* __restrict__ gi, const float* __restrict__ gh,
                      float* __restrict__ h) {
    int row = blockIdx.x;
    const float* gip = gi + (size_t)row * G_;
    const float* ghp = gh + (size_t)row * G_;
    float* hp = h + (size_t)row * D_;
    #pragma unroll
    for (int d = threadIdx.x; d < D_; d += 256) {
        float ir = gip[d], iz = gip[D_ + d], in = gip[2 * D_ + d];
        float hr = ghp[d], hz = ghp[D_ + d], hn = ghp[2 * D_ + d];
        float r = 1.0f / (1.0f + expf(-(ir + hr)));
        float z = 1.0f / (1.0f + expf(-(iz + hz)));
        float n = tanhf(in + r * hn);
        hp[d] = (1.0f - z) * n + z * hp[d];
    }
}

__global__ void k_out(const float* __restrict__ h, const int* __restrict__ keep,
                      float* __restrict__ out) {
    int bw = blockIdx.x;
    int b = bw >> 9;
    int wn = bw & 511;
    int kp = keep[b]; if (kp > 512) kp = 512;
    bool valid = wn < kp;
    const float4* hp = (const float4*)(h + (size_t)bw * D_);
    float4* op = (float4*)(out + (size_t)bw * D_);
    int d = threadIdx.x;
    float4 v = valid ? hp[d] : make_float4(0.f, 0.f, 0.f, 0.f);
    op[d] = v;
}

// ================= launch =================
extern "C" void kernel_launch(void* const* d_in, const int* in_sizes, int n_in,
                              void* d_out, int out_size) {
    const int*   node_types = (const int*)d_in[0];
    const int*   tok_ids    = (const int*)d_in[1];
    const int*   seg_ids    = (const int*)d_in[2]; (void)seg_ids;
    const int*   tok_lens   = (const int*)d_in[3];
    const int*   gnode_lens = (const int*)d_in[4];
    const int*   esrc       = (const int*)d_in[5];
    const int*   edst       = (const int*)d_in[6];
    const float* ew         = (const float*)d_in[7];
    const float* type_table = (const float*)d_in[8];
    const float* word_emb   = (const float*)d_in[9];
    const float* fusion_w   = (const float*)d_in[10];
    const float* fusion_b   = (const float*)d_in[11];
    const float* ggnn_w     = (const float*)d_in[12];
    const float* w_ih       = (const float*)d_in[13];
    const float* w_hh       = (const float*)d_in[14];
    const float* b_ih       = (const float*)d_in[15];
    const float* b_hh       = (const float*)d_in[16];
    float* out = (float*)d_out;

    cudaFuncSetAttribute(bmma, cudaFuncAttributeMaxDynamicSharedMemorySize, SMEM_SZ);

    // one-time side stream + events (host objects; created on first call only)
    static cudaStream_t s1 = nullptr;
    static cudaEvent_t eH = nullptr, eG = nullptr, eW = nullptr;
    if (!s1) {
        cudaStreamCreateWithFlags(&s1, cudaStreamNonBlocking);
        cudaEventCreateWithFlags(&eH, cudaEventDisableTiming);
        cudaEventCreateWithFlags(&eG, cudaEventDisableTiming);
        cudaEventCreateWithFlags(&eW, cudaEventDisableTiming);
    }

    float *fused, *h, *msg, *agg, *gi, *gh;
    cudaGetSymbolAddress((void**)&fused, g_fused);
    cudaGetSymbolAddress((void**)&h,     g_h);
    cudaGetSymbolAddress((void**)&msg,   g_msg);
    cudaGetSymbolAddress((void**)&agg,   g_agg);
    cudaGetSymbolAddress((void**)&gi,    g_gi);
    cudaGetSymbolAddress((void**)&gh,    g_gh);

    __half *fw, *gw, *ih, *hh;
    cudaGetSymbolAddress((void**)&fw, s_fw);
    cudaGetSymbolAddress((void**)&gw, s_gw);
    cudaGetSymbolAddress((void**)&ih, s_ih);
    cudaGetSymbolAddress((void**)&hh, s_hh);

    int *cnt, *off, *pos, *src_s; float *w_s;
    cudaGetSymbolAddress((void**)&cnt,   g_cnt);
    cudaGetSymbolAddress((void**)&off,   g_off);
    cudaGetSymbolAddress((void**)&pos,   g_pos);
    cudaGetSymbolAddress((void**)&src_s, g_src_s);
    cudaGetSymbolAddress((void**)&w_s,   g_w_s);

    // ---- fork: side stream does gw/ih/hh conversions + CSR build ----
    cudaEventRecord(eH, 0);                 // capture-origin ordering point
    cudaStreamWaitEvent(s1, eH, 0);
    k_cvt_tb<<<(L_ * D_ * D_ + 255) / 256, 256, 0, s1>>>(ggnn_w, gw);
    k_cvt<<<(G_ * D_ + 255) / 256, 256, 0, s1>>>(w_ih, ih, G_ * D_);
    k_cvt<<<(G_ * D_ + 255) / 256, 256, 0, s1>>>(w_hh, hh, G_ * D_);
    k_zero_i<<<(B_ * N_ + 255) / 256, 256, 0, s1>>>(cnt, B_ * N_);
    k_count<<<(B_ * E_ + 255) / 256, 256, 0, s1>>>(edst, cnt);
    k_prefix<<<B_, N_, 0, s1>>>(cnt, off, pos);
    k_fill<<<(B_ * E_ + 255) / 256, 256, 0, s1>>>(esrc, edst, ew, pos, src_s, w_s);
    cudaEventRecord(eW, s1);

    // ---- main stream: fw cvt, embed, fusion GEMM ----
    k_cvt_t<<<(F_ * D_ + 255) / 256, 256>>>(fusion_w, fw, F_, D_);
    k_embed<<<M_, 192>>>(node_types, tok_ids, tok_lens, type_table, word_emb, fused);
    bmma<<<dim3(D_ / 128, M_ / 128), 256, SMEM_SZ>>>(fused, fw, fusion_b, h, D_, F_);

    cudaStreamWaitEvent(0, eW, 0);          // need gw/ih/hh + CSR below

    for (int l = 0; l < L_; ++l) {
        // h is ready here; fork gh onto side stream
        cudaEventRecord(eH, 0);
        cudaStreamWaitEvent(s1, eH, 0);
        bmma<<<dim3(G_ / 128, M_ / 128), 256, SMEM_SZ, s1>>>(h, hh, b_hh, gh, G_, D_);
        cudaEventRecord(eG, s1);

        // main chain: msg -> gather -> gi
        bmma<<<dim3(D_ / 128, M_ / 128), 256, SMEM_SZ>>>(
            h, gw + (size_t)l * D_ * D_, nullptr, msg, D_, D_);
        k_gather<<<M_, 192>>>(off, src_s, w_s, msg, agg);
        bmma<<<dim3(G_ / 128, M_ / 128), 256, SMEM_SZ>>>(agg, ih, b_ih, gi, G_, D_);

        // join, then GRU
        cudaStreamWaitEvent(0, eG, 0);
        k_gru<<<M_, 256>>>(gi, gh, h);
    }

    k_out<<<M_, 192>>>(h, gnode_lens, out);
}